// round 6
// baseline (speedup 1.0000x reference)
#include <cuda_runtime.h>
#include <math.h>
#include <stdint.h>

// Problem constants
#define B_   32
#define T_   2000
#define DE_  512
#define DD_  1024
#define A_   128
#define FN_  32
#define FS_  16
#define KW_  33    // 2*FS+1

// Scratch (no cudaMalloc allowed)
__device__ float g_eff[KW_ * A_];        // eff[k][a] = sum_f att_w[a,f]*conv_w[f,k]
__device__ float g_pd[B_ * A_];          // dec projection + att_b
__device__ float g_score[B_ * T_];       // pre-softmax scores (masked with -inf)
__device__ float g_partial[8 * B_ * DE_];// split-T context partials

// ---------------------------------------------------------------------------
// K0: fold conv weights through att_w.  1 block, 128 threads (thread = a).
// ---------------------------------------------------------------------------
__global__ void k_eff(const float* __restrict__ att_w, const float* __restrict__ conv_w) {
    int a = threadIdx.x;
    float aw[FN_];
#pragma unroll
    for (int f = 0; f < FN_; ++f) aw[f] = att_w[a * FN_ + f];
    for (int k = 0; k < KW_; ++k) {
        float s = 0.f;
#pragma unroll
        for (int f = 0; f < FN_; ++f) s = fmaf(aw[f], conv_w[f * KW_ + k], s);
        g_eff[k * A_ + a] = s;
    }
}

// ---------------------------------------------------------------------------
// K1: projected_dec[b,a] + att_b[a].  grid B_, 128 threads (thread = a).
// ---------------------------------------------------------------------------
__global__ void k_pd(const float* __restrict__ dec_w, const float* __restrict__ input_dec,
                     const float* __restrict__ att_b) {
    __shared__ float sdec[DD_];
    int b = blockIdx.x, tid = threadIdx.x;
    for (int i = tid; i < DD_; i += blockDim.x) sdec[i] = input_dec[b * DD_ + i];
    __syncthreads();
    int a = tid;
    const float4* wr = (const float4*)(dec_w + (size_t)a * DD_);
    const float4* xr = (const float4*)sdec;
    float s = 0.f;
#pragma unroll 4
    for (int i = 0; i < DD_ / 4; ++i) {
        float4 w = wr[i], x = xr[i];
        s = fmaf(w.x, x.x, fmaf(w.y, x.y, fmaf(w.z, x.z, fmaf(w.w, x.w, s))));
    }
    g_pd[b * A_ + a] = s + att_b[a];
}

// ---------------------------------------------------------------------------
// K2: fused score GEMM.
//   Per block: (b, t-tile of 128).  C[128t x 128a] = enc_tile[128x512] @ enc_w.T
//   using packed f32x2 FMAs, then epilogue: + pd + location-FIR, tanh, dot out_w,
//   length mask -> g_score.
// ---------------------------------------------------------------------------
#define BM 128
#define BN 128
#define BK 16
#define LDT 132   // padded tile stride (floats), keeps 16B alignment (132*4=528)

__global__ __launch_bounds__(256, 2)
void k_score(const float* __restrict__ enc, const float* __restrict__ enc_w,
             const float* __restrict__ prev_att, const float* __restrict__ out_w,
             const int* __restrict__ lengths)
{
    __shared__ __align__(16) float smem[4640];
    float* As = smem;              // [BK][LDT]  A-tile transposed: As[k][m]
    float* Bs = smem + BK * LDT;   // [BK][LDT]  B-tile transposed: Bs[k][a]

    const int b     = blockIdx.y;
    const int trow0 = blockIdx.x * BM;
    const int tid   = threadIdx.x;
    const int tx    = tid & 15;    // a-block  (8 cols each)
    const int ty    = tid >> 4;    // t-block  (8 rows each)
    const int lr    = tid >> 2;    // load row 0..63
    const int lc    = tid & 3;     // load col-quad 0..3

    unsigned long long acc2[8][4]; // 8 rows x 4 f32x2 pairs (= 8x8 fp32)
#pragma unroll
    for (int i = 0; i < 8; ++i)
#pragma unroll
        for (int j = 0; j < 4; ++j) acc2[i][j] = 0ull;

    const float* Abase = enc + ((size_t)b * T_ + trow0) * DE_;

    for (int kt = 0; kt < DE_; kt += BK) {
        // ---- load A tile (guard t >= T with zeros) ----
#pragma unroll
        for (int h = 0; h < 2; ++h) {
            int m = lr + 64 * h;
            float4 v = make_float4(0.f, 0.f, 0.f, 0.f);
            if (trow0 + m < T_)
                v = *(const float4*)(Abase + (size_t)m * DE_ + kt + lc * 4);
            As[(lc * 4 + 0) * LDT + m] = v.x;
            As[(lc * 4 + 1) * LDT + m] = v.y;
            As[(lc * 4 + 2) * LDT + m] = v.z;
            As[(lc * 4 + 3) * LDT + m] = v.w;
        }
        // ---- load B tile (enc_w is exactly [128][512]) ----
#pragma unroll
        for (int h = 0; h < 2; ++h) {
            int a = lr + 64 * h;
            float4 v = *(const float4*)(enc_w + (size_t)a * DE_ + kt + lc * 4);
            Bs[(lc * 4 + 0) * LDT + a] = v.x;
            Bs[(lc * 4 + 1) * LDT + a] = v.y;
            Bs[(lc * 4 + 2) * LDT + a] = v.z;
            Bs[(lc * 4 + 3) * LDT + a] = v.w;
        }
        __syncthreads();

#pragma unroll
        for (int k = 0; k < BK; ++k) {
            float4 a0 = *(const float4*)(As + k * LDT + ty * 8);
            float4 a1 = *(const float4*)(As + k * LDT + ty * 8 + 4);
            ulonglong2 b01 = *(const ulonglong2*)(Bs + k * LDT + tx * 8);
            ulonglong2 b23 = *(const ulonglong2*)(Bs + k * LDT + tx * 8 + 4);
            float av[8] = {a0.x, a0.y, a0.z, a0.w, a1.x, a1.y, a1.z, a1.w};
#pragma unroll
            for (int i = 0; i < 8; ++i) {
                unsigned long long ad;
                asm("mov.b64 %0, {%1, %1};" : "=l"(ad) : "r"(__float_as_uint(av[i])));
                asm("fma.rn.f32x2 %0, %1, %2, %0;" : "+l"(acc2[i][0]) : "l"(ad), "l"(b01.x));
                asm("fma.rn.f32x2 %0, %1, %2, %0;" : "+l"(acc2[i][1]) : "l"(ad), "l"(b01.y));
                asm("fma.rn.f32x2 %0, %1, %2, %0;" : "+l"(acc2[i][2]) : "l"(ad), "l"(b23.x));
                asm("fma.rn.f32x2 %0, %1, %2, %0;" : "+l"(acc2[i][3]) : "l"(ad), "l"(b23.y));
            }
        }
        __syncthreads();
    }

    // ---- unpack accumulators ----
    float acc[8][8];
#pragma unroll
    for (int i = 0; i < 8; ++i)
#pragma unroll
        for (int j2 = 0; j2 < 4; ++j2) {
            unsigned lo, hi;
            asm("mov.b64 {%0, %1}, %2;" : "=r"(lo), "=r"(hi) : "l"(acc2[i][j2]));
            acc[i][2 * j2]     = __uint_as_float(lo);
            acc[i][2 * j2 + 1] = __uint_as_float(hi);
        }

    // ---- epilogue shared: reuse GEMM smem (already synced above) ----
    float* effs = smem;            // [KW_][A_] = 4224 floats
    float* patt = smem + 4224;     // 160 floats (128 + 2*FS halo)
    float* cbs  = smem + 4384;     // 128 (pd + att_b)
    float* ows  = smem + 4512;     // 128 (out_w)
    for (int idx = tid; idx < KW_ * A_; idx += 256) effs[idx] = g_eff[idx];
    for (int idx = tid; idx < BM + 2 * FS_; idx += 256) {
        int t = trow0 + idx - FS_;
        patt[idx] = (t >= 0 && t < T_) ? prev_att[b * T_ + t] : 0.f;
    }
    if (tid < A_) { cbs[tid] = g_pd[b * A_ + tid]; ows[tid] = out_w[tid]; }
    __syncthreads();

    float cbv[8], owv[8];
#pragma unroll
    for (int j = 0; j < 8; ++j) { cbv[j] = cbs[tx * 8 + j]; owv[j] = ows[tx * 8 + j]; }
#pragma unroll
    for (int i = 0; i < 8; ++i)
#pragma unroll
        for (int j = 0; j < 8; ++j) acc[i][j] += cbv[j];

    const int rowRel = ty * 8;
    // location term: acc[i][j] += sum_k eff[j][k] * prev_att[t + k - FS]
#pragma unroll 3
    for (int k = 0; k < KW_; ++k) {
        float4 e0 = *(const float4*)(effs + k * A_ + tx * 8);
        float4 e1 = *(const float4*)(effs + k * A_ + tx * 8 + 4);
#pragma unroll
        for (int i = 0; i < 8; ++i) {
            float pv = patt[rowRel + i + k];
            acc[i][0] = fmaf(e0.x, pv, acc[i][0]);
            acc[i][1] = fmaf(e0.y, pv, acc[i][1]);
            acc[i][2] = fmaf(e0.z, pv, acc[i][2]);
            acc[i][3] = fmaf(e0.w, pv, acc[i][3]);
            acc[i][4] = fmaf(e1.x, pv, acc[i][4]);
            acc[i][5] = fmaf(e1.y, pv, acc[i][5]);
            acc[i][6] = fmaf(e1.z, pv, acc[i][6]);
            acc[i][7] = fmaf(e1.w, pv, acc[i][7]);
        }
    }

    const int len = lengths[b];
#pragma unroll
    for (int i = 0; i < 8; ++i) {
        float p = 0.f;
#pragma unroll
        for (int j = 0; j < 8; ++j) p = fmaf(owv[j], tanhf(acc[i][j]), p);
        // reduce over the 16 tx lanes (a half-warp: lanes are contiguous)
        p += __shfl_down_sync(0xffffffffu, p, 8, 16);
        p += __shfl_down_sync(0xffffffffu, p, 4, 16);
        p += __shfl_down_sync(0xffffffffu, p, 2, 16);
        p += __shfl_down_sync(0xffffffffu, p, 1, 16);
        int t = trow0 + rowRel + i;
        if (tx == 0 && t < T_)
            g_score[b * T_ + t] = (t < len) ? p : -INFINITY;
    }
}

// ---------------------------------------------------------------------------
// K3: masked softmax per batch row.  grid B_, 256 threads.
// ---------------------------------------------------------------------------
__global__ void k_softmax(float* __restrict__ att_out) {
    int b = blockIdx.x, tid = threadIdx.x;
    __shared__ float red[256];
    const float* sc = g_score + b * T_;

    float m = -INFINITY;
    for (int t = tid; t < T_; t += 256) m = fmaxf(m, sc[t]);
    red[tid] = m; __syncthreads();
    for (int s = 128; s > 0; s >>= 1) {
        if (tid < s) red[tid] = fmaxf(red[tid], red[tid + s]);
        __syncthreads();
    }
    m = red[0]; __syncthreads();

    float sum = 0.f;
    for (int t = tid; t < T_; t += 256) sum += expf(sc[t] - m);
    red[tid] = sum; __syncthreads();
    for (int s = 128; s > 0; s >>= 1) {
        if (tid < s) red[tid] += red[tid + s];
        __syncthreads();
    }
    float inv = 1.f / red[0];

    for (int t = tid; t < T_; t += 256)
        att_out[b * T_ + t] = expf(sc[t] - m) * inv;   // exp(-inf)=0 handles mask
}

// ---------------------------------------------------------------------------
// K4: context partials, split over T.  grid (B_, 8), 512 threads (thread = d).
// ---------------------------------------------------------------------------
__global__ void k_context(const float* __restrict__ enc, const float* __restrict__ att,
                          const int* __restrict__ lengths) {
    int b = blockIdx.x, seg = blockIdx.y;
    int d = threadIdx.x;
    int len = lengths[b];
    int t0 = seg * (T_ / 8);
    int t1 = min(t0 + (T_ / 8), len);   // weights are exactly 0 past len
    float s = 0.f;
    const float* ebase = enc + ((size_t)b * T_) * DE_ + d;
    const float* arow  = att + b * T_;
#pragma unroll 4
    for (int t = t0; t < t1; ++t)
        s = fmaf(arow[t], ebase[(size_t)t * DE_], s);
    g_partial[(seg * B_ + b) * DE_ + d] = s;
}

__global__ void k_reduce(float* __restrict__ ctx_out) {
    int b = blockIdx.x, d = threadIdx.x;
    float s = 0.f;
#pragma unroll
    for (int seg = 0; seg < 8; ++seg) s += g_partial[(seg * B_ + b) * DE_ + d];
    ctx_out[b * DE_ + d] = s;
}

// ---------------------------------------------------------------------------
// Entry point
// ---------------------------------------------------------------------------
extern "C" void kernel_launch(void* const* d_in, const int* in_sizes, int n_in,
                              void* d_out, int out_size) {
    const float* input_enc   = (const float*)d_in[0];
    const int*   enc_lengths = (const int*)  d_in[1];
    const float* input_dec   = (const float*)d_in[2];
    const float* prev_att    = (const float*)d_in[3];
    const float* conv_w      = (const float*)d_in[4];
    const float* enc_w       = (const float*)d_in[5];
    const float* dec_w       = (const float*)d_in[6];
    const float* att_w       = (const float*)d_in[7];
    const float* att_b       = (const float*)d_in[8];
    const float* out_w       = (const float*)d_in[9];

    float* ctx_out = (float*)d_out;            // [B, DE]
    float* att_out = ctx_out + B_ * DE_;       // [B, T]

    k_eff<<<1, 128>>>(att_w, conv_w);
    k_pd<<<B_, 128>>>(dec_w, input_dec, att_b);
    k_score<<<dim3((T_ + BM - 1) / BM, B_), 256>>>(input_enc, enc_w, prev_att, out_w, enc_lengths);
    k_softmax<<<B_, 256>>>(att_out);
    k_context<<<dim3(B_, 8), 512>>>(input_enc, att_out, enc_lengths);
    k_reduce<<<B_, 512>>>(ctx_out);
}

// round 8
// speedup vs baseline: 1.8774x; 1.8774x over previous
#include <cuda_runtime.h>
#include <math.h>
#include <stdint.h>

// Problem constants
#define B_   32
#define T_   2000
#define DE_  512
#define DD_  1024
#define A_   128
#define FN_  32
#define FS_  16
#define KW_  33

#define TILE_M 128
#define BKF    16            // K floats per chunk
#define NCHG   32            // gmem K-chunks (512/16)
#define NCH_TOT 35           // +3 ext chunks (FIR taps + bias)
#define LDS_   20            // padded smem row stride (floats): conflict-free
#define SEG_   16
#define TSEG   (T_/SEG_)     // 125

// Scratch (no cudaMalloc allowed)
__device__ float g_eff[KW_ * A_];        // eff[k][a]
__device__ float g_pd[B_ * A_];          // dec projection + att_b
__device__ float g_score[B_ * T_];
__device__ float g_stats[B_ * 2];        // max, 1/sum
__device__ float g_partial[SEG_ * B_ * DE_];

__device__ __forceinline__ uint32_t f2tf32(float x) {
    uint32_t r; asm("cvt.rna.tf32.f32 %0, %1;" : "=r"(r) : "f"(x)); return r;
}
__device__ __forceinline__ void mma_tf32(float* d, const uint32_t* a, const uint32_t* bb) {
    asm volatile(
        "mma.sync.aligned.m16n8k8.row.col.f32.tf32.tf32.f32 "
        "{%0,%1,%2,%3}, {%4,%5,%6,%7}, {%8,%9}, {%0,%1,%2,%3};"
        : "+f"(d[0]), "+f"(d[1]), "+f"(d[2]), "+f"(d[3])
        : "r"(a[0]), "r"(a[1]), "r"(a[2]), "r"(a[3]), "r"(bb[0]), "r"(bb[1]));
}

// ---------------------------------------------------------------------------
// K0: fold conv weights through att_w.  1 block, 128 threads.
// ---------------------------------------------------------------------------
__global__ void k_eff(const float* __restrict__ att_w, const float* __restrict__ conv_w) {
    int a = threadIdx.x;
    float aw[FN_];
#pragma unroll
    for (int f = 0; f < FN_; ++f) aw[f] = att_w[a * FN_ + f];
    for (int k = 0; k < KW_; ++k) {
        float s = 0.f;
#pragma unroll
        for (int f = 0; f < FN_; ++f) s = fmaf(aw[f], conv_w[f * KW_ + k], s);
        g_eff[k * A_ + a] = s;
    }
}

// ---------------------------------------------------------------------------
// K1: decoder projection + att_b.  grid B_, 128 threads.
// ---------------------------------------------------------------------------
__global__ void k_pd(const float* __restrict__ dec_w, const float* __restrict__ input_dec,
                     const float* __restrict__ att_b) {
    __shared__ float sdec[DD_];
    int b = blockIdx.x, tid = threadIdx.x;
    for (int i = tid; i < DD_; i += blockDim.x) sdec[i] = input_dec[b * DD_ + i];
    __syncthreads();
    const float4* wr = (const float4*)(dec_w + (size_t)tid * DD_);
    const float4* xr = (const float4*)sdec;
    float s = 0.f;
#pragma unroll 4
    for (int i = 0; i < DD_ / 4; ++i) {
        float4 w = wr[i], x = xr[i];
        s = fmaf(w.x, x.x, fmaf(w.y, x.y, fmaf(w.z, x.z, fmaf(w.w, x.w, s))));
    }
    g_pd[b * A_ + tid] = s + att_b[tid];
}

// ---------------------------------------------------------------------------
// K2: tf32 mma.sync score GEMM, FIR + bias folded as extra K.
//   Per CTA (b, t-tile of 128): D[128t x 128a], K = 512 + 48(ext).
//   8 warps; warp tile 64x32 = 4x4 m16n8k8 tiles.
// ---------------------------------------------------------------------------
__global__ void __launch_bounds__(256)
k_score(const float* __restrict__ enc, const float* __restrict__ enc_w,
        const float* __restrict__ prev_att, const float* __restrict__ out_w,
        const int* __restrict__ lengths)
{
    __shared__ float As[2][TILE_M * LDS_];   // [t-rows][k] padded
    __shared__ float Bs[2][TILE_M * LDS_];   // [a-rows][k] padded
    __shared__ float spatt[TILE_M + 2 * FS_];
    __shared__ float s_ow[A_];
    __shared__ float sred[4][TILE_M];

    const int b     = blockIdx.y;
    const int trow0 = blockIdx.x * TILE_M;
    const int tid   = threadIdx.x;
    const int lane  = tid & 31;
    const int wid   = tid >> 5;
    const int warp_m = wid & 1;       // 0..1 -> 64 rows
    const int warp_n = wid >> 1;      // 0..3 -> 32 cols
    const int g     = lane >> 2;      // group id 0..7
    const int tg    = lane & 3;       // thread-in-group 0..3

    // loader geometry: thread covers rows r and r+64, float4 quad q
    const int r = tid >> 2;
    const int q = tid & 3;

    for (int i = tid; i < TILE_M + 2 * FS_; i += 256) {
        int t = trow0 + i - FS_;
        spatt[i] = (t >= 0 && t < T_) ? prev_att[b * T_ + t] : 0.f;
    }
    if (tid < A_) s_ow[tid] = out_w[tid];

    float acc[4][4][4];
#pragma unroll
    for (int mi = 0; mi < 4; ++mi)
#pragma unroll
        for (int ni = 0; ni < 4; ++ni)
#pragma unroll
            for (int j = 0; j < 4; ++j) acc[mi][ni][j] = 0.f;

    const float4 z4 = make_float4(0.f, 0.f, 0.f, 0.f);
    const float* Ab = enc + ((size_t)b * T_ + trow0) * DE_;
    float4 ra0, ra1, rb0, rb1;

    auto gload = [&](int c) {
        const int kt = c * BKF + q * 4;
        ra0 = (trow0 + r      < T_) ? *(const float4*)(Ab + (size_t)r        * DE_ + kt) : z4;
        ra1 = (trow0 + r + 64 < T_) ? *(const float4*)(Ab + (size_t)(r + 64) * DE_ + kt) : z4;
        rb0 = *(const float4*)(enc_w + (size_t)r        * DE_ + kt);
        rb1 = *(const float4*)(enc_w + (size_t)(r + 64) * DE_ + kt);
    };
    auto sts4 = [&](float* dst, float4 v) {
        dst[0] = __uint_as_float(f2tf32(v.x));
        dst[1] = __uint_as_float(f2tf32(v.y));
        dst[2] = __uint_as_float(f2tf32(v.z));
        dst[3] = __uint_as_float(f2tf32(v.w));
    };
    // build ext-chunk values (FIR taps / bias) for row rr, chunk e=c-32
    auto extvals = [&](int e, int rr, float4& av, float4& bv) {
        if (e == 0) {
            av = make_float4(spatt[rr + 4*q], spatt[rr + 4*q + 1],
                             spatt[rr + 4*q + 2], spatt[rr + 4*q + 3]);
            bv = make_float4(g_eff[(4*q + 0) * A_ + rr], g_eff[(4*q + 1) * A_ + rr],
                             g_eff[(4*q + 2) * A_ + rr], g_eff[(4*q + 3) * A_ + rr]);
        } else if (e == 1) {
            av = make_float4(spatt[rr + 16 + 4*q], spatt[rr + 16 + 4*q + 1],
                             spatt[rr + 16 + 4*q + 2], spatt[rr + 16 + 4*q + 3]);
            bv = make_float4(g_eff[(16 + 4*q + 0) * A_ + rr], g_eff[(16 + 4*q + 1) * A_ + rr],
                             g_eff[(16 + 4*q + 2) * A_ + rr], g_eff[(16 + 4*q + 3) * A_ + rr]);
        } else {
            av = z4; bv = z4;
            if (q == 0) {
                av.x = spatt[rr + 32]; av.y = 1.0f;
                bv.x = g_eff[32 * A_ + rr]; bv.y = g_pd[b * A_ + rr];
            }
        }
    };

    gload(0);
    __syncthreads();   // spatt/s_ow ready

    for (int c = 0; c < NCH_TOT; ++c) {
        const int bi = c & 1;
        float* Ad = &As[bi][0];
        float* Bd = &Bs[bi][0];
        if (c < NCHG) {
            sts4(Ad + r * LDS_ + 4*q, ra0);
            sts4(Ad + (r + 64) * LDS_ + 4*q, ra1);
            sts4(Bd + r * LDS_ + 4*q, rb0);
            sts4(Bd + (r + 64) * LDS_ + 4*q, rb1);
            if (c + 1 < NCHG) gload(c + 1);
        } else {
            float4 av, bv;
            extvals(c - 32, r, av, bv);
            sts4(Ad + r * LDS_ + 4*q, av);
            sts4(Bd + r * LDS_ + 4*q, bv);
            extvals(c - 32, r + 64, av, bv);
            sts4(Ad + (r + 64) * LDS_ + 4*q, av);
            sts4(Bd + (r + 64) * LDS_ + 4*q, bv);
        }
        __syncthreads();

#pragma unroll
        for (int step = 0; step < 2; ++step) {
            const int k0 = tg + 8 * step;
            uint32_t af[4][4], bf[4][2];
#pragma unroll
            for (int mi = 0; mi < 4; ++mi) {
                int rb = warp_m * 64 + mi * 16 + g;
                af[mi][0] = __float_as_uint(Ad[rb * LDS_ + k0]);
                af[mi][1] = __float_as_uint(Ad[(rb + 8) * LDS_ + k0]);
                af[mi][2] = __float_as_uint(Ad[rb * LDS_ + k0 + 4]);
                af[mi][3] = __float_as_uint(Ad[(rb + 8) * LDS_ + k0 + 4]);
            }
#pragma unroll
            for (int ni = 0; ni < 4; ++ni) {
                int nb = warp_n * 32 + ni * 8 + g;
                bf[ni][0] = __float_as_uint(Bd[nb * LDS_ + k0]);
                bf[ni][1] = __float_as_uint(Bd[nb * LDS_ + k0 + 4]);
            }
#pragma unroll
            for (int mi = 0; mi < 4; ++mi)
#pragma unroll
                for (int ni = 0; ni < 4; ++ni)
                    mma_tf32(acc[mi][ni], af[mi], bf[ni]);
        }
        // note: single sync per iter is safe with double buffering
    }
    __syncthreads();

    // ---- epilogue: tanh + out_w dot, reduce over the a dimension ----
    // thread's cols: c0 = warp_n*32 + ni*8 + 2*tg, c1 = c0+1
    float ow0[4], ow1[4];
#pragma unroll
    for (int ni = 0; ni < 4; ++ni) {
        int c0 = warp_n * 32 + ni * 8 + 2 * tg;
        ow0[ni] = s_ow[c0]; ow1[ni] = s_ow[c0 + 1];
    }
#pragma unroll
    for (int mi = 0; mi < 4; ++mi) {
        float p0 = 0.f, p1 = 0.f;   // rows rb and rb+8
#pragma unroll
        for (int ni = 0; ni < 4; ++ni) {
            p0 = fmaf(ow0[ni], tanhf(acc[mi][ni][0]), p0);
            p0 = fmaf(ow1[ni], tanhf(acc[mi][ni][1]), p0);
            p1 = fmaf(ow0[ni], tanhf(acc[mi][ni][2]), p1);
            p1 = fmaf(ow1[ni], tanhf(acc[mi][ni][3]), p1);
        }
        // reduce across the 4 lanes of the quad (width 4)
        p0 += __shfl_down_sync(0xffffffffu, p0, 2, 4);
        p0 += __shfl_down_sync(0xffffffffu, p0, 1, 4);
        p1 += __shfl_down_sync(0xffffffffu, p1, 2, 4);
        p1 += __shfl_down_sync(0xffffffffu, p1, 1, 4);
        if (tg == 0) {
            int rb = warp_m * 64 + mi * 16 + g;
            sred[warp_n][rb] = p0;
            sred[warp_n][rb + 8] = p1;
        }
    }
    __syncthreads();

    if (tid < TILE_M) {
        int t = trow0 + tid;
        if (t < T_) {
            float s = sred[0][tid] + sred[1][tid] + sred[2][tid] + sred[3][tid];
            g_score[b * T_ + t] = (t < lengths[b]) ? s : -INFINITY;
        }
    }
}

// ---------------------------------------------------------------------------
// K3: per-batch softmax stats (max, 1/sum).  grid B_, 1024 threads.
// ---------------------------------------------------------------------------
__global__ void k_stats() {
    int b = blockIdx.x, tid = threadIdx.x;
    __shared__ float red[32];
    __shared__ float s_m;
    const float* sc = g_score + b * T_;

    float m = -INFINITY;
    for (int t = tid; t < T_; t += 1024) m = fmaxf(m, sc[t]);
#pragma unroll
    for (int o = 16; o; o >>= 1) m = fmaxf(m, __shfl_xor_sync(0xffffffffu, m, o));
    if ((tid & 31) == 0) red[tid >> 5] = m;
    __syncthreads();
    if (tid < 32) {
        float v = red[tid];
#pragma unroll
        for (int o = 16; o; o >>= 1) v = fmaxf(v, __shfl_xor_sync(0xffffffffu, v, o));
        if (tid == 0) s_m = v;
    }
    __syncthreads();
    m = s_m;

    float s = 0.f;
    for (int t = tid; t < T_; t += 1024) s += expf(sc[t] - m);
#pragma unroll
    for (int o = 16; o; o >>= 1) s += __shfl_xor_sync(0xffffffffu, s, o);
    if ((tid & 31) == 0) red[tid >> 5] = s;
    __syncthreads();
    if (tid < 32) {
        float v = red[tid];
#pragma unroll
        for (int o = 16; o; o >>= 1) v += __shfl_xor_sync(0xffffffffu, v, o);
        if (tid == 0) { g_stats[2 * b] = m; g_stats[2 * b + 1] = 1.f / v; }
    }
}

// ---------------------------------------------------------------------------
// K4: fused att-weight write + context partials.  grid (B_, SEG_), 512 threads.
// ---------------------------------------------------------------------------
__global__ void k_ctx(const float* __restrict__ enc, float* __restrict__ att_out,
                      const int* __restrict__ lengths) {
    int b = blockIdx.x, seg = blockIdx.y, tid = threadIdx.x;
    __shared__ float w[TSEG];
    const float m = g_stats[2 * b], inv = g_stats[2 * b + 1];
    const int t0 = seg * TSEG;
    if (tid < TSEG) {
        float sc = g_score[b * T_ + t0 + tid];
        float wv = expf(sc - m) * inv;       // exp(-inf)=0 handles the mask
        w[tid] = wv;
        att_out[b * T_ + t0 + tid] = wv;
    }
    __syncthreads();
    const int len = lengths[b];
    const int n = min(TSEG, max(0, len - t0));
    float s = 0.f;
    const float* e = enc + ((size_t)b * T_ + t0) * DE_ + tid;
#pragma unroll 4
    for (int tt = 0; tt < n; ++tt) s = fmaf(w[tt], e[(size_t)tt * DE_], s);
    g_partial[(seg * B_ + b) * DE_ + tid] = s;
}

__global__ void k_reduce(float* __restrict__ ctx_out) {
    int b = blockIdx.x, d = threadIdx.x;
    float s = 0.f;
#pragma unroll
    for (int seg = 0; seg < SEG_; ++seg) s += g_partial[(seg * B_ + b) * DE_ + d];
    ctx_out[b * DE_ + d] = s;
}

// ---------------------------------------------------------------------------
// Entry point
// ---------------------------------------------------------------------------
extern "C" void kernel_launch(void* const* d_in, const int* in_sizes, int n_in,
                              void* d_out, int out_size) {
    const float* input_enc   = (const float*)d_in[0];
    const int*   enc_lengths = (const int*)  d_in[1];
    const float* input_dec   = (const float*)d_in[2];
    const float* prev_att    = (const float*)d_in[3];
    const float* conv_w      = (const float*)d_in[4];
    const float* enc_w       = (const float*)d_in[5];
    const float* dec_w       = (const float*)d_in[6];
    const float* att_w       = (const float*)d_in[7];
    const float* att_b       = (const float*)d_in[8];
    const float* out_w       = (const float*)d_in[9];

    float* ctx_out = (float*)d_out;            // [B, DE]
    float* att_out = ctx_out + B_ * DE_;       // [B, T]

    k_eff<<<1, 128>>>(att_w, conv_w);
    k_pd<<<B_, 128>>>(dec_w, input_dec, att_b);
    k_score<<<dim3((T_ + TILE_M - 1) / TILE_M, B_), 256>>>(input_enc, enc_w, prev_att, out_w, enc_lengths);
    k_stats<<<B_, 1024>>>();
    k_ctx<<<dim3(B_, SEG_), 512>>>(input_enc, att_out, enc_lengths);
    k_reduce<<<B_, 512>>>(ctx_out);
}

// round 9
// speedup vs baseline: 2.2944x; 1.2221x over previous
#include <cuda_runtime.h>
#include <math.h>
#include <stdint.h>

// Problem constants
#define B_   32
#define T_   2000
#define DE_  512
#define DD_  1024
#define A_   128
#define FN_  32
#define FS_  16
#define KW_  33

#define TILE_M 128
#define BKF    16            // K floats per chunk
#define NCHG   32            // gmem K-chunks (512/16)
#define LDS_   20            // padded smem row stride (floats): conflict-free
#define SEG_   16
#define TSEG   (T_/SEG_)     // 125

// dynamic smem layout (float offsets): 4 A bufs, 4 B bufs, spatt, ow, red
#define ABUF(i)  ((i) * 2560)            // 128*20
#define BBUF(i)  (10240 + (i) * 2560)
#define SPATT_O  20480
#define SOW_O    20640
#define SRED_O   20768
#define SMEM_FLOATS 21280                // 85120 bytes

// Scratch (no cudaMalloc allowed)
__device__ float g_eff[KW_ * A_];        // eff[k][a]
__device__ float g_pd[B_ * A_];          // dec projection + att_b
__device__ float g_score[B_ * T_];
__device__ float g_stats[B_ * 2];        // max, 1/sum
__device__ float g_partial[SEG_ * B_ * DE_];

__device__ __forceinline__ uint32_t smem_u32(const void* p) {
    uint32_t a;
    asm("{ .reg .u64 t; cvta.to.shared.u64 t, %1; cvt.u32.u64 %0, t; }" : "=r"(a) : "l"(p));
    return a;
}
__device__ __forceinline__ uint32_t f2tf32(float x) {
    uint32_t r; asm("cvt.rna.tf32.f32 %0, %1;" : "=r"(r) : "f"(x)); return r;
}
__device__ __forceinline__ void cp16(uint32_t dst, uint64_t src, int srcsz) {
    asm volatile("cp.async.cg.shared.global [%0], [%1], 16, %2;"
                 :: "r"(dst), "l"(src), "r"(srcsz) : "memory");
}
__device__ __forceinline__ void mma_tf32(float* d, const uint32_t* a, const uint32_t* bb) {
    asm volatile(
        "mma.sync.aligned.m16n8k8.row.col.f32.tf32.tf32.f32 "
        "{%0,%1,%2,%3}, {%4,%5,%6,%7}, {%8,%9}, {%0,%1,%2,%3};"
        : "+f"(d[0]), "+f"(d[1]), "+f"(d[2]), "+f"(d[3])
        : "r"(a[0]), "r"(a[1]), "r"(a[2]), "r"(a[3]), "r"(bb[0]), "r"(bb[1]));
}

// ---------------------------------------------------------------------------
// K0: fold conv weights through att_w.  1 block, 128 threads.
// ---------------------------------------------------------------------------
__global__ void k_eff(const float* __restrict__ att_w, const float* __restrict__ conv_w) {
    int a = threadIdx.x;
    float aw[FN_];
#pragma unroll
    for (int f = 0; f < FN_; ++f) aw[f] = att_w[a * FN_ + f];
    for (int k = 0; k < KW_; ++k) {
        float s = 0.f;
#pragma unroll
        for (int f = 0; f < FN_; ++f) s = fmaf(aw[f], conv_w[f * KW_ + k], s);
        g_eff[k * A_ + a] = s;
    }
}

// ---------------------------------------------------------------------------
// K1: decoder projection + att_b.  grid B_, 128 threads.
// ---------------------------------------------------------------------------
__global__ void k_pd(const float* __restrict__ dec_w, const float* __restrict__ input_dec,
                     const float* __restrict__ att_b) {
    __shared__ float sdec[DD_];
    int b = blockIdx.x, tid = threadIdx.x;
    for (int i = tid; i < DD_; i += blockDim.x) sdec[i] = input_dec[b * DD_ + i];
    __syncthreads();
    const float4* wr = (const float4*)(dec_w + (size_t)tid * DD_);
    const float4* xr = (const float4*)sdec;
    float s = 0.f;
#pragma unroll 4
    for (int i = 0; i < DD_ / 4; ++i) {
        float4 w = wr[i], x = xr[i];
        s = fmaf(w.x, x.x, fmaf(w.y, x.y, fmaf(w.z, x.z, fmaf(w.w, x.w, s))));
    }
    g_pd[b * A_ + tid] = s + att_b[tid];
}

// ---------------------------------------------------------------------------
// K2: tf32 mma.sync score GEMM, cp.async 4-buffer pipeline,
//     FIR + bias folded as extra K chunks.  8 warps; warp tile 64x32.
// ---------------------------------------------------------------------------
__global__ void __launch_bounds__(256, 2)
k_score(const float* __restrict__ enc, const float* __restrict__ enc_w,
        const float* __restrict__ prev_att, const float* __restrict__ out_w,
        const int* __restrict__ lengths)
{
    extern __shared__ float dsm[];

    const int b     = blockIdx.y;
    const int trow0 = blockIdx.x * TILE_M;
    const int tid   = threadIdx.x;
    const int lane  = tid & 31;
    const int wid   = tid >> 5;
    const int warp_m = wid & 1;
    const int warp_n = wid >> 1;
    const int g     = lane >> 2;
    const int tg    = lane & 3;
    const int r     = tid >> 2;     // loader row 0..63 (covers r and r+64)
    const int q     = tid & 3;      // loader quad

    const int len = lengths[b];
    if (trow0 >= len) {             // fully masked tile: skip all GEMM work
        for (int i = tid; i < TILE_M; i += 256) {
            int t = trow0 + i;
            if (t < T_) g_score[b * T_ + t] = -INFINITY;
        }
        return;
    }

    float* spatt = dsm + SPATT_O;   // 160
    float* s_ow  = dsm + SOW_O;     // 128
    float* sred  = dsm + SRED_O;    // 4*128

    for (int i = tid; i < TILE_M + 2 * FS_; i += 256) {
        int t = trow0 + i - FS_;
        spatt[i] = (t >= 0 && t < T_) ? prev_att[b * T_ + t] : 0.f;
    }
    if (tid < A_) s_ow[tid] = out_w[tid];

    const uint32_t sbase = smem_u32(dsm);
    uint64_t gA, gW;
    {
        const float* Abase = enc + ((size_t)b * T_ + trow0) * DE_;
        asm("cvta.to.global.u64 %0, %1;" : "=l"(gA) : "l"(Abase));
        asm("cvta.to.global.u64 %0, %1;" : "=l"(gW) : "l"(enc_w));
    }
    const int szA0 = (trow0 + r      < T_) ? 16 : 0;
    const int szA1 = (trow0 + r + 64 < T_) ? 16 : 0;
    const uint32_t soff     = (uint32_t)(r * LDS_ + 4 * q) * 4u;
    const uint32_t rowskip  = 64u * LDS_ * 4u;           // 5120 B
    const uint64_t goff     = ((size_t)r * DE_ + 4 * q) * 4;
    const uint64_t growskip = (size_t)64 * DE_ * 4;

    auto issue = [&](int c) {
        const int bi = c & 3;
        const uint32_t da = sbase + (uint32_t)ABUF(bi) * 4u + soff;
        const uint32_t db = sbase + (uint32_t)BBUF(bi) * 4u + soff;
        const uint64_t off = goff + (uint64_t)c * (BKF * 4);
        cp16(da,           gA + off,            szA0);
        cp16(da + rowskip, gA + off + growskip, szA1);
        cp16(db,           gW + off,            16);
        cp16(db + rowskip, gW + off + growskip, 16);
        asm volatile("cp.async.commit_group;" ::: "memory");
    };

    float acc[4][4][4];
#pragma unroll
    for (int mi = 0; mi < 4; ++mi)
#pragma unroll
        for (int ni = 0; ni < 4; ++ni)
#pragma unroll
            for (int j = 0; j < 4; ++j) acc[mi][ni][j] = 0.f;

    auto compute = [&](int bi) {
        const float* Ad = dsm + ABUF(bi);
        const float* Bd = dsm + BBUF(bi);
#pragma unroll
        for (int step = 0; step < 2; ++step) {
            const int k0 = tg + 8 * step;
            uint32_t af[4][4], bf[4][2];
#pragma unroll
            for (int mi = 0; mi < 4; ++mi) {
                int rb = warp_m * 64 + mi * 16 + g;
                af[mi][0] = f2tf32(Ad[rb * LDS_ + k0]);
                af[mi][1] = f2tf32(Ad[(rb + 8) * LDS_ + k0]);
                af[mi][2] = f2tf32(Ad[rb * LDS_ + k0 + 4]);
                af[mi][3] = f2tf32(Ad[(rb + 8) * LDS_ + k0 + 4]);
            }
#pragma unroll
            for (int ni = 0; ni < 4; ++ni) {
                int nb = warp_n * 32 + ni * 8 + g;
                bf[ni][0] = f2tf32(Bd[nb * LDS_ + k0]);
                bf[ni][1] = f2tf32(Bd[nb * LDS_ + k0 + 4]);
            }
#pragma unroll
            for (int mi = 0; mi < 4; ++mi)
#pragma unroll
                for (int ni = 0; ni < 4; ++ni)
                    mma_tf32(acc[mi][ni], af[mi], bf[ni]);
        }
    };

    // ext-chunk writer (FIR taps / bias) into buffer bi, chunk e in {0,1,2}
    auto sts4 = [&](float* dst, float4 v) {
        dst[0] = __uint_as_float(f2tf32(v.x));
        dst[1] = __uint_as_float(f2tf32(v.y));
        dst[2] = __uint_as_float(f2tf32(v.z));
        dst[3] = __uint_as_float(f2tf32(v.w));
    };
    auto extsts = [&](int e, int bi) {
        float* Ad = dsm + ABUF(bi);
        float* Bd = dsm + BBUF(bi);
        const float4 z4 = make_float4(0.f, 0.f, 0.f, 0.f);
#pragma unroll
        for (int h = 0; h < 2; ++h) {
            const int rr = r + 64 * h;
            float4 av, bv;
            if (e < 2) {
                const int kk = 16 * e + 4 * q;
                av = make_float4(spatt[rr + kk], spatt[rr + kk + 1],
                                 spatt[rr + kk + 2], spatt[rr + kk + 3]);
                bv = make_float4(g_eff[(kk + 0) * A_ + rr], g_eff[(kk + 1) * A_ + rr],
                                 g_eff[(kk + 2) * A_ + rr], g_eff[(kk + 3) * A_ + rr]);
            } else {
                av = z4; bv = z4;
                if (q == 0) {
                    av.x = spatt[rr + 32]; av.y = 1.0f;
                    bv.x = g_eff[32 * A_ + rr]; bv.y = g_pd[b * A_ + rr];
                }
            }
            sts4(Ad + rr * LDS_ + 4 * q, av);
            sts4(Bd + rr * LDS_ + 4 * q, bv);
        }
    };

    // ---- pipelined mainloop over 32 gmem chunks ----
    issue(0);
    issue(1);
    for (int c = 0; c < NCHG; ++c) {
        if (c + 2 < NCHG) {
            issue(c + 2);
            asm volatile("cp.async.wait_group 2;" ::: "memory");
        } else if (c + 1 < NCHG) {
            asm volatile("cp.async.wait_group 1;" ::: "memory");
        } else {
            asm volatile("cp.async.wait_group 0;" ::: "memory");
        }
        __syncthreads();
        compute(c & 3);
    }

    // ---- ext chunks: FIR taps 0..31 (e=0,1) + tap32 & bias (e=2) ----
    // bufs 0,1,2 are free of pending cp.async and not read by compute(31) (buf 3)
    extsts(0, 0); extsts(1, 1); extsts(2, 2);
    __syncthreads();
    compute(0); compute(1); compute(2);

    // ---- epilogue: tanh + out_w dot, reduce over a-dimension ----
    float ow0[4], ow1[4];
#pragma unroll
    for (int ni = 0; ni < 4; ++ni) {
        int c0 = warp_n * 32 + ni * 8 + 2 * tg;
        ow0[ni] = s_ow[c0]; ow1[ni] = s_ow[c0 + 1];
    }
#pragma unroll
    for (int mi = 0; mi < 4; ++mi) {
        float p0 = 0.f, p1 = 0.f;
#pragma unroll
        for (int ni = 0; ni < 4; ++ni) {
            p0 = fmaf(ow0[ni], tanhf(acc[mi][ni][0]), p0);
            p0 = fmaf(ow1[ni], tanhf(acc[mi][ni][1]), p0);
            p1 = fmaf(ow0[ni], tanhf(acc[mi][ni][2]), p1);
            p1 = fmaf(ow1[ni], tanhf(acc[mi][ni][3]), p1);
        }
        p0 += __shfl_down_sync(0xffffffffu, p0, 2, 4);
        p0 += __shfl_down_sync(0xffffffffu, p0, 1, 4);
        p1 += __shfl_down_sync(0xffffffffu, p1, 2, 4);
        p1 += __shfl_down_sync(0xffffffffu, p1, 1, 4);
        if (tg == 0) {
            int rb = warp_m * 64 + mi * 16 + g;
            sred[warp_n * TILE_M + rb] = p0;
            sred[warp_n * TILE_M + rb + 8] = p1;
        }
    }
    __syncthreads();

    if (tid < TILE_M) {
        int t = trow0 + tid;
        if (t < T_) {
            float s = sred[tid] + sred[TILE_M + tid] +
                      sred[2 * TILE_M + tid] + sred[3 * TILE_M + tid];
            g_score[b * T_ + t] = (t < len) ? s : -INFINITY;
        }
    }
}

// ---------------------------------------------------------------------------
// K3: per-batch softmax stats (max, 1/sum).  grid B_, 1024 threads.
// ---------------------------------------------------------------------------
__global__ void k_stats() {
    int b = blockIdx.x, tid = threadIdx.x;
    __shared__ float red[32];
    __shared__ float s_m;
    const float* sc = g_score + b * T_;

    float m = -INFINITY;
    for (int t = tid; t < T_; t += 1024) m = fmaxf(m, sc[t]);
#pragma unroll
    for (int o = 16; o; o >>= 1) m = fmaxf(m, __shfl_xor_sync(0xffffffffu, m, o));
    if ((tid & 31) == 0) red[tid >> 5] = m;
    __syncthreads();
    if (tid < 32) {
        float v = red[tid];
#pragma unroll
        for (int o = 16; o; o >>= 1) v = fmaxf(v, __shfl_xor_sync(0xffffffffu, v, o));
        if (tid == 0) s_m = v;
    }
    __syncthreads();
    m = s_m;

    float s = 0.f;
    for (int t = tid; t < T_; t += 1024) s += expf(sc[t] - m);
#pragma unroll
    for (int o = 16; o; o >>= 1) s += __shfl_xor_sync(0xffffffffu, s, o);
    if ((tid & 31) == 0) red[tid >> 5] = s;
    __syncthreads();
    if (tid < 32) {
        float v = red[tid];
#pragma unroll
        for (int o = 16; o; o >>= 1) v += __shfl_xor_sync(0xffffffffu, v, o);
        if (tid == 0) { g_stats[2 * b] = m; g_stats[2 * b + 1] = 1.f / v; }
    }
}

// ---------------------------------------------------------------------------
// K4: fused att-weight write + context partials.  grid (B_, SEG_), 512 threads.
// ---------------------------------------------------------------------------
__global__ void k_ctx(const float* __restrict__ enc, float* __restrict__ att_out,
                      const int* __restrict__ lengths) {
    int b = blockIdx.x, seg = blockIdx.y, tid = threadIdx.x;
    __shared__ float w[TSEG];
    const float m = g_stats[2 * b], inv = g_stats[2 * b + 1];
    const int t0 = seg * TSEG;
    if (tid < TSEG) {
        float sc = g_score[b * T_ + t0 + tid];
        float wv = expf(sc - m) * inv;       // exp(-inf)=0 handles the mask
        w[tid] = wv;
        att_out[b * T_ + t0 + tid] = wv;
    }
    __syncthreads();
    const int len = lengths[b];
    const int n = min(TSEG, max(0, len - t0));
    float s = 0.f;
    const float* e = enc + ((size_t)b * T_ + t0) * DE_ + tid;
#pragma unroll 4
    for (int tt = 0; tt < n; ++tt) s = fmaf(w[tt], e[(size_t)tt * DE_], s);
    g_partial[(seg * B_ + b) * DE_ + tid] = s;
}

__global__ void k_reduce(float* __restrict__ ctx_out) {
    int b = blockIdx.x, d = threadIdx.x;
    float s = 0.f;
#pragma unroll
    for (int seg = 0; seg < SEG_; ++seg) s += g_partial[(seg * B_ + b) * DE_ + d];
    ctx_out[b * DE_ + d] = s;
}

// ---------------------------------------------------------------------------
// Entry point
// ---------------------------------------------------------------------------
extern "C" void kernel_launch(void* const* d_in, const int* in_sizes, int n_in,
                              void* d_out, int out_size) {
    const float* input_enc   = (const float*)d_in[0];
    const int*   enc_lengths = (const int*)  d_in[1];
    const float* input_dec   = (const float*)d_in[2];
    const float* prev_att    = (const float*)d_in[3];
    const float* conv_w      = (const float*)d_in[4];
    const float* enc_w       = (const float*)d_in[5];
    const float* dec_w       = (const float*)d_in[6];
    const float* att_w       = (const float*)d_in[7];
    const float* att_b       = (const float*)d_in[8];
    const float* out_w       = (const float*)d_in[9];

    float* ctx_out = (float*)d_out;            // [B, DE]
    float* att_out = ctx_out + B_ * DE_;       // [B, T]

    static int attr_set = 0;
    if (!attr_set) {
        cudaFuncSetAttribute(k_score, cudaFuncAttributeMaxDynamicSharedMemorySize,
                             SMEM_FLOATS * 4);
        attr_set = 1;
    }

    k_eff<<<1, 128>>>(att_w, conv_w);
    k_pd<<<B_, 128>>>(dec_w, input_dec, att_b);
    k_score<<<dim3((T_ + TILE_M - 1) / TILE_M, B_), 256, SMEM_FLOATS * 4>>>(
        input_enc, enc_w, prev_att, out_w, enc_lengths);
    k_stats<<<B_, 1024>>>();
    k_ctx<<<dim3(B_, SEG_), 512>>>(input_enc, att_out, enc_lengths);
    k_reduce<<<B_, 512>>>(ctx_out);
}

// round 10
// speedup vs baseline: 2.3008x; 1.0028x over previous
#include <cuda_runtime.h>
#include <math.h>
#include <stdint.h>

// Problem constants
#define B_   32
#define T_   2000
#define DE_  512
#define DD_  1024
#define A_   128
#define FN_  32
#define FS_  16
#define KW_  33

#define TILE_M 128
#define BKF    16            // K floats per chunk
#define NCHG   32            // gmem K-chunks (512/16)
#define NBUF   5
#define LDS_   20            // padded smem row stride (floats): conflict-free
#define SEG_   20
#define TSEG   (T_/SEG_)     // 100

// dynamic smem layout (float offsets): 5 A bufs, 5 B bufs, spatt, ow, red
#define ABUF(i)  ((i) * 2560)             // 128*20
#define BBUF(i)  (12800 + (i) * 2560)
#define SPATT_O  25600
#define SOW_O    25760
#define SRED_O   25888
#define SMEM_FLOATS 26400                 // 105600 bytes

// Scratch (no cudaMalloc allowed)
__device__ float g_eff[KW_ * A_];        // eff[k][a]
__device__ float g_pd[B_ * A_];          // dec projection + att_b
__device__ float g_wt[A_ * DE_];         // enc_w pre-rounded to tf32
__device__ float g_score[B_ * T_];
__device__ float g_stats[B_ * 2];        // max, 1/sum

__device__ __forceinline__ uint32_t smem_u32(const void* p) {
    uint32_t a;
    asm("{ .reg .u64 t; cvta.to.shared.u64 t, %1; cvt.u32.u64 %0, t; }" : "=r"(a) : "l"(p));
    return a;
}
__device__ __forceinline__ uint32_t f2tf32(float x) {
    uint32_t r; asm("cvt.rna.tf32.f32 %0, %1;" : "=r"(r) : "f"(x)); return r;
}
__device__ __forceinline__ void cp16(uint32_t dst, uint64_t src, int srcsz) {
    asm volatile("cp.async.cg.shared.global [%0], [%1], 16, %2;"
                 :: "r"(dst), "l"(src), "r"(srcsz) : "memory");
}
__device__ __forceinline__ void mma_tf32(float* d, const uint32_t* a, const uint32_t* bb) {
    asm volatile(
        "mma.sync.aligned.m16n8k8.row.col.f32.tf32.tf32.f32 "
        "{%0,%1,%2,%3}, {%4,%5,%6,%7}, {%8,%9}, {%0,%1,%2,%3};"
        : "+f"(d[0]), "+f"(d[1]), "+f"(d[2]), "+f"(d[3])
        : "r"(a[0]), "r"(a[1]), "r"(a[2]), "r"(a[3]), "r"(bb[0]), "r"(bb[1]));
}

// ---------------------------------------------------------------------------
// K0: fold conv weights through att_w.  1 block, 128 threads.
// ---------------------------------------------------------------------------
__global__ void k_eff(const float* __restrict__ att_w, const float* __restrict__ conv_w) {
    int a = threadIdx.x;
    float aw[FN_];
#pragma unroll
    for (int f = 0; f < FN_; ++f) aw[f] = att_w[a * FN_ + f];
    for (int k = 0; k < KW_; ++k) {
        float s = 0.f;
#pragma unroll
        for (int f = 0; f < FN_; ++f) s = fmaf(aw[f], conv_w[f * KW_ + k], s);
        g_eff[k * A_ + a] = s;
    }
}

// ---------------------------------------------------------------------------
// K1: decoder projection + att_b; pre-round enc_w to tf32; zero ctx_out.
//     grid B_, 128 threads.
// ---------------------------------------------------------------------------
__global__ void k_pd(const float* __restrict__ dec_w, const float* __restrict__ input_dec,
                     const float* __restrict__ att_b, const float* __restrict__ enc_w,
                     float* __restrict__ ctx_out) {
    __shared__ float sdec[DD_];
    int b = blockIdx.x, tid = threadIdx.x;
    int gt = b * 128 + tid;                       // 4096 global threads
    for (int i = tid; i < DD_; i += blockDim.x) sdec[i] = input_dec[b * DD_ + i];
    // pre-round enc_w: 65536 elems / 4096 threads = 16 each
    for (int i = gt; i < A_ * DE_; i += B_ * 128)
        g_wt[i] = __uint_as_float(f2tf32(enc_w[i]));
    // zero ctx accumulators (re-done every launch -> graph-replay safe)
    for (int i = gt; i < B_ * DE_; i += B_ * 128) ctx_out[i] = 0.f;
    __syncthreads();
    const float4* wr = (const float4*)(dec_w + (size_t)tid * DD_);
    const float4* xr = (const float4*)sdec;
    float s = 0.f;
#pragma unroll 4
    for (int i = 0; i < DD_ / 4; ++i) {
        float4 w = wr[i], x = xr[i];
        s = fmaf(w.x, x.x, fmaf(w.y, x.y, fmaf(w.z, x.z, fmaf(w.w, x.w, s))));
    }
    g_pd[b * A_ + tid] = s + att_b[tid];
}

// ---------------------------------------------------------------------------
// K2: tf32 mma.sync score GEMM, cp.async 5-buffer depth-3 pipeline,
//     FIR + bias folded as extra K chunks.  8 warps; warp tile 64x32.
// ---------------------------------------------------------------------------
__global__ void __launch_bounds__(256, 2)
k_score(const float* __restrict__ enc, const float* __restrict__ prev_att,
        const float* __restrict__ out_w, const int* __restrict__ lengths)
{
    extern __shared__ float dsm[];

    const int b     = blockIdx.y;
    const int trow0 = blockIdx.x * TILE_M;
    const int tid   = threadIdx.x;
    const int lane  = tid & 31;
    const int wid   = tid >> 5;
    const int warp_m = wid & 1;
    const int warp_n = wid >> 1;
    const int g     = lane >> 2;
    const int tg    = lane & 3;
    const int r     = tid >> 2;     // loader row 0..63 (covers r and r+64)
    const int q     = tid & 3;      // loader quad

    const int len = lengths[b];
    if (trow0 >= len) {             // fully masked tile
        for (int i = tid; i < TILE_M; i += 256) {
            int t = trow0 + i;
            if (t < T_) g_score[b * T_ + t] = -INFINITY;
        }
        return;
    }

    float* spatt = dsm + SPATT_O;
    float* s_ow  = dsm + SOW_O;
    float* sred  = dsm + SRED_O;

    for (int i = tid; i < TILE_M + 2 * FS_; i += 256) {
        int t = trow0 + i - FS_;
        spatt[i] = (t >= 0 && t < T_) ? prev_att[b * T_ + t] : 0.f;
    }
    if (tid < A_) s_ow[tid] = out_w[tid];

    const uint32_t sbase = smem_u32(dsm);
    uint64_t gA, gW;
    {
        const float* Abase = enc + ((size_t)b * T_ + trow0) * DE_;
        const float* Wbase = g_wt;
        asm("cvta.to.global.u64 %0, %1;" : "=l"(gA) : "l"(Abase));
        asm("cvta.to.global.u64 %0, %1;" : "=l"(gW) : "l"(Wbase));
    }
    const int szA0 = (trow0 + r      < T_) ? 16 : 0;
    const int szA1 = (trow0 + r + 64 < T_) ? 16 : 0;
    const uint32_t soff     = (uint32_t)(r * LDS_ + 4 * q) * 4u;
    const uint32_t rowskip  = 64u * LDS_ * 4u;
    const uint64_t goff     = ((size_t)r * DE_ + 4 * q) * 4;
    const uint64_t growskip = (size_t)64 * DE_ * 4;

    auto issue = [&](int c) {
        const int bi = c % NBUF;
        const uint32_t da = sbase + (uint32_t)ABUF(bi) * 4u + soff;
        const uint32_t db = sbase + (uint32_t)BBUF(bi) * 4u + soff;
        const uint64_t off = goff + (uint64_t)c * (BKF * 4);
        cp16(da,           gA + off,            szA0);
        cp16(da + rowskip, gA + off + growskip, szA1);
        cp16(db,           gW + off,            16);
        cp16(db + rowskip, gW + off + growskip, 16);
        asm volatile("cp.async.commit_group;" ::: "memory");
    };

    float acc[4][4][4];
#pragma unroll
    for (int mi = 0; mi < 4; ++mi)
#pragma unroll
        for (int ni = 0; ni < 4; ++ni)
#pragma unroll
            for (int j = 0; j < 4; ++j) acc[mi][ni][j] = 0.f;

    // register-lean compute: bf[8] + af[4] live at a time
    auto compute = [&](int bi) {
        const float* Ad = dsm + ABUF(bi);
        const float* Bd = dsm + BBUF(bi);
#pragma unroll
        for (int step = 0; step < 2; ++step) {
            const int k0 = tg + 8 * step;
            uint32_t bf[4][2];
#pragma unroll
            for (int ni = 0; ni < 4; ++ni) {
                int nb = warp_n * 32 + ni * 8 + g;
                bf[ni][0] = __float_as_uint(Bd[nb * LDS_ + k0]);      // pre-rounded
                bf[ni][1] = __float_as_uint(Bd[nb * LDS_ + k0 + 4]);
            }
#pragma unroll
            for (int mi = 0; mi < 4; ++mi) {
                int rb = warp_m * 64 + mi * 16 + g;
                uint32_t af[4];
                af[0] = f2tf32(Ad[rb * LDS_ + k0]);
                af[1] = f2tf32(Ad[(rb + 8) * LDS_ + k0]);
                af[2] = f2tf32(Ad[rb * LDS_ + k0 + 4]);
                af[3] = f2tf32(Ad[(rb + 8) * LDS_ + k0 + 4]);
#pragma unroll
                for (int ni = 0; ni < 4; ++ni)
                    mma_tf32(acc[mi][ni], af, bf[ni]);
            }
        }
    };

    auto sts4 = [&](float* dst, float4 v) {
        dst[0] = __uint_as_float(f2tf32(v.x));
        dst[1] = __uint_as_float(f2tf32(v.y));
        dst[2] = __uint_as_float(f2tf32(v.z));
        dst[3] = __uint_as_float(f2tf32(v.w));
    };
    auto extsts = [&](int e, int bi) {
        float* Ad = dsm + ABUF(bi);
        float* Bd = dsm + BBUF(bi);
        const float4 z4 = make_float4(0.f, 0.f, 0.f, 0.f);
#pragma unroll
        for (int h = 0; h < 2; ++h) {
            const int rr = r + 64 * h;
            float4 av, bv;
            if (e < 2) {
                const int kk = 16 * e + 4 * q;
                av = make_float4(spatt[rr + kk], spatt[rr + kk + 1],
                                 spatt[rr + kk + 2], spatt[rr + kk + 3]);
                bv = make_float4(g_eff[(kk + 0) * A_ + rr], g_eff[(kk + 1) * A_ + rr],
                                 g_eff[(kk + 2) * A_ + rr], g_eff[(kk + 3) * A_ + rr]);
            } else {
                av = z4; bv = z4;
                if (q == 0) {
                    av.x = spatt[rr + 32]; av.y = 1.0f;
                    bv.x = g_eff[32 * A_ + rr]; bv.y = g_pd[b * A_ + rr];
                }
            }
            sts4(Ad + rr * LDS_ + 4 * q, av);
            sts4(Bd + rr * LDS_ + 4 * q, bv);
        }
    };

    // ---- pipelined mainloop: depth-3 prefetch over 5 buffers ----
    issue(0); issue(1); issue(2);
    for (int c = 0; c < NCHG; ++c) {
        if (c + 3 < NCHG) {
            issue(c + 3);
            asm volatile("cp.async.wait_group 3;" ::: "memory");
        } else if (c + 2 < NCHG) {
            asm volatile("cp.async.wait_group 2;" ::: "memory");
        } else if (c + 1 < NCHG) {
            asm volatile("cp.async.wait_group 1;" ::: "memory");
        } else {
            asm volatile("cp.async.wait_group 0;" ::: "memory");
        }
        __syncthreads();
        compute(c % NBUF);
    }

    // ---- ext chunks in bufs 2,3,4 (drained; chunk 31 ran in buf 1) ----
    extsts(0, 2); extsts(1, 3); extsts(2, 4);
    __syncthreads();
    compute(2); compute(3); compute(4);

    // ---- epilogue: tanh + out_w dot, reduce over a-dimension ----
    float ow0[4], ow1[4];
#pragma unroll
    for (int ni = 0; ni < 4; ++ni) {
        int c0 = warp_n * 32 + ni * 8 + 2 * tg;
        ow0[ni] = s_ow[c0]; ow1[ni] = s_ow[c0 + 1];
    }
#pragma unroll
    for (int mi = 0; mi < 4; ++mi) {
        float p0 = 0.f, p1 = 0.f;
#pragma unroll
        for (int ni = 0; ni < 4; ++ni) {
            p0 = fmaf(ow0[ni], tanhf(acc[mi][ni][0]), p0);
            p0 = fmaf(ow1[ni], tanhf(acc[mi][ni][1]), p0);
            p1 = fmaf(ow0[ni], tanhf(acc[mi][ni][2]), p1);
            p1 = fmaf(ow1[ni], tanhf(acc[mi][ni][3]), p1);
        }
        p0 += __shfl_down_sync(0xffffffffu, p0, 2, 4);
        p0 += __shfl_down_sync(0xffffffffu, p0, 1, 4);
        p1 += __shfl_down_sync(0xffffffffu, p1, 2, 4);
        p1 += __shfl_down_sync(0xffffffffu, p1, 1, 4);
        if (tg == 0) {
            int rb = warp_m * 64 + mi * 16 + g;
            sred[warp_n * TILE_M + rb] = p0;
            sred[warp_n * TILE_M + rb + 8] = p1;
        }
    }
    __syncthreads();

    if (tid < TILE_M) {
        int t = trow0 + tid;
        if (t < T_) {
            float s = sred[tid] + sred[TILE_M + tid] +
                      sred[2 * TILE_M + tid] + sred[3 * TILE_M + tid];
            g_score[b * T_ + t] = (t < len) ? s : -INFINITY;
        }
    }
}

// ---------------------------------------------------------------------------
// K3: per-batch softmax stats (max, 1/sum).  grid B_, 1024 threads.
// ---------------------------------------------------------------------------
__global__ void k_stats() {
    int b = blockIdx.x, tid = threadIdx.x;
    __shared__ float red[32];
    __shared__ float s_m;
    const float* sc = g_score + b * T_;

    float m = -INFINITY;
    for (int t = tid; t < T_; t += 1024) m = fmaxf(m, sc[t]);
#pragma unroll
    for (int o = 16; o; o >>= 1) m = fmaxf(m, __shfl_xor_sync(0xffffffffu, m, o));
    if ((tid & 31) == 0) red[tid >> 5] = m;
    __syncthreads();
    if (tid < 32) {
        float v = red[tid];
#pragma unroll
        for (int o = 16; o; o >>= 1) v = fmaxf(v, __shfl_xor_sync(0xffffffffu, v, o));
        if (tid == 0) s_m = v;
    }
    __syncthreads();
    m = s_m;

    float s = 0.f;
    for (int t = tid; t < T_; t += 1024) s += expf(sc[t] - m);
#pragma unroll
    for (int o = 16; o; o >>= 1) s += __shfl_xor_sync(0xffffffffu, s, o);
    if ((tid & 31) == 0) red[tid >> 5] = s;
    __syncthreads();
    if (tid < 32) {
        float v = red[tid];
#pragma unroll
        for (int o = 16; o; o >>= 1) v += __shfl_xor_sync(0xffffffffu, v, o);
        if (tid == 0) { g_stats[2 * b] = m; g_stats[2 * b + 1] = 1.f / v; }
    }
}

// ---------------------------------------------------------------------------
// K4: fused att-weight write + context atomic accumulate.
//     grid (B_, SEG_), 512 threads.
// ---------------------------------------------------------------------------
__global__ void k_ctx(const float* __restrict__ enc, float* __restrict__ att_out,
                      float* __restrict__ ctx_out, const int* __restrict__ lengths) {
    int b = blockIdx.x, seg = blockIdx.y, tid = threadIdx.x;
    __shared__ float w[TSEG];
    const float m = g_stats[2 * b], inv = g_stats[2 * b + 1];
    const int t0 = seg * TSEG;
    if (tid < TSEG) {
        float sc = g_score[b * T_ + t0 + tid];
        float wv = expf(sc - m) * inv;       // exp(-inf)=0 handles the mask
        w[tid] = wv;
        att_out[b * T_ + t0 + tid] = wv;
    }
    __syncthreads();
    const int len = lengths[b];
    const int n = min(TSEG, max(0, len - t0));
    float s = 0.f;
    const float* e = enc + ((size_t)b * T_ + t0) * DE_ + tid;
#pragma unroll 4
    for (int tt = 0; tt < n; ++tt) s = fmaf(w[tt], e[(size_t)tt * DE_], s);
    if (n > 0) atomicAdd(&ctx_out[b * DE_ + tid], s);
}

// ---------------------------------------------------------------------------
// Entry point
// ---------------------------------------------------------------------------
extern "C" void kernel_launch(void* const* d_in, const int* in_sizes, int n_in,
                              void* d_out, int out_size) {
    const float* input_enc   = (const float*)d_in[0];
    const int*   enc_lengths = (const int*)  d_in[1];
    const float* input_dec   = (const float*)d_in[2];
    const float* prev_att    = (const float*)d_in[3];
    const float* conv_w      = (const float*)d_in[4];
    const float* enc_w       = (const float*)d_in[5];
    const float* dec_w       = (const float*)d_in[6];
    const float* att_w       = (const float*)d_in[7];
    const float* att_b       = (const float*)d_in[8];
    const float* out_w       = (const float*)d_in[9];

    float* ctx_out = (float*)d_out;            // [B, DE]
    float* att_out = ctx_out + B_ * DE_;       // [B, T]

    static int attr_set = 0;
    if (!attr_set) {
        cudaFuncSetAttribute(k_score, cudaFuncAttributeMaxDynamicSharedMemorySize,
                             SMEM_FLOATS * 4);
        attr_set = 1;
    }

    k_eff<<<1, 128>>>(att_w, conv_w);
    k_pd<<<B_, 128>>>(dec_w, input_dec, att_b, enc_w, ctx_out);
    k_score<<<dim3((T_ + TILE_M - 1) / TILE_M, B_), 256, SMEM_FLOATS * 4>>>(
        input_enc, prev_att, out_w, enc_lengths);
    k_stats<<<B_, 1024>>>();
    k_ctx<<<dim3(B_, SEG_), 512>>>(input_enc, att_out, ctx_out, enc_lengths);
}

// round 11
// speedup vs baseline: 2.6758x; 1.1630x over previous
#include <cuda_runtime.h>
#include <math.h>
#include <stdint.h>

// Problem constants
#define B_   32
#define T_   2000
#define DE_  512
#define DD_  1024
#define A_   128
#define FN_  32
#define FS_  16
#define KW_  33

#define TILE_M 128
#define BKF    16            // K floats per chunk (= one m16n8k16 slab)
#define NCHG   32            // gmem K-chunks (512/16)
#define NBUF   4
#define LDS_   24            // padded smem row stride (floats): conflict-free for LDS.64
#define SEG_   20
#define TSEG   (T_/SEG_)     // 100

// dynamic smem layout (float offsets): 4 A bufs, 4 B bufs, spatt, ow, red
#define ABUF(i)  ((i) * 3072)             // 128*24
#define BBUF(i)  (12288 + (i) * 3072)
#define SPATT_O  24576
#define SOW_O    24736
#define SRED_O   24864
#define SMEM_FLOATS 25376                 // 101504 bytes

// Scratch (no cudaMalloc allowed)
__device__ float g_eff[KW_ * A_];        // eff[k][a]
__device__ float g_pd[B_ * A_];          // dec projection + att_b
__device__ float g_score[B_ * T_];
__device__ float g_stats[B_ * 2];        // max, 1/sum

__device__ __forceinline__ uint32_t smem_u32(const void* p) {
    uint32_t a;
    asm("{ .reg .u64 t; cvta.to.shared.u64 t, %1; cvt.u32.u64 %0, t; }" : "=r"(a) : "l"(p));
    return a;
}
__device__ __forceinline__ void cp16(uint32_t dst, uint64_t src, int srcsz) {
    asm volatile("cp.async.cg.shared.global [%0], [%1], 16, %2;"
                 :: "r"(dst), "l"(src), "r"(srcsz) : "memory");
}
// load two consecutive k floats, round to fp16 pair {lo=k, hi=k+1}
__device__ __forceinline__ uint32_t packh2(const float* p) {
    float2 v = *(const float2*)p;
    uint32_t r;
    asm("cvt.rn.f16x2.f32 %0, %1, %2;" : "=r"(r) : "f"(v.y), "f"(v.x));
    return r;
}
__device__ __forceinline__ void mma_f16(float* d, const uint32_t* a, const uint32_t* bb) {
    asm volatile(
        "mma.sync.aligned.m16n8k16.row.col.f32.f16.f16.f32 "
        "{%0,%1,%2,%3}, {%4,%5,%6,%7}, {%8,%9}, {%0,%1,%2,%3};"
        : "+f"(d[0]), "+f"(d[1]), "+f"(d[2]), "+f"(d[3])
        : "r"(a[0]), "r"(a[1]), "r"(a[2]), "r"(a[3]), "r"(bb[0]), "r"(bb[1]));
}

// ---------------------------------------------------------------------------
// K0: fold conv weights through att_w.  1 block, 128 threads.
// ---------------------------------------------------------------------------
__global__ void k_eff(const float* __restrict__ att_w, const float* __restrict__ conv_w) {
    int a = threadIdx.x;
    float aw[FN_];
#pragma unroll
    for (int f = 0; f < FN_; ++f) aw[f] = att_w[a * FN_ + f];
    for (int k = 0; k < KW_; ++k) {
        float s = 0.f;
#pragma unroll
        for (int f = 0; f < FN_; ++f) s = fmaf(aw[f], conv_w[f * KW_ + k], s);
        g_eff[k * A_ + a] = s;
    }
}

// ---------------------------------------------------------------------------
// K0b: zero ctx accumulators (graph-replay safe).  Also positions k_score at
//      launch index 3, which is the launch ncu captures.
// ---------------------------------------------------------------------------
__global__ void k_zero(float* __restrict__ ctx_out) {
    ctx_out[blockIdx.x * 512 + threadIdx.x] = 0.f;
}

// ---------------------------------------------------------------------------
// K1: decoder projection + att_b.  grid B_, 128 threads.
// ---------------------------------------------------------------------------
__global__ void k_pd(const float* __restrict__ dec_w, const float* __restrict__ input_dec,
                     const float* __restrict__ att_b) {
    __shared__ float sdec[DD_];
    int b = blockIdx.x, tid = threadIdx.x;
    for (int i = tid; i < DD_; i += blockDim.x) sdec[i] = input_dec[b * DD_ + i];
    __syncthreads();
    const float4* wr = (const float4*)(dec_w + (size_t)tid * DD_);
    const float4* xr = (const float4*)sdec;
    float s = 0.f;
#pragma unroll 4
    for (int i = 0; i < DD_ / 4; ++i) {
        float4 w = wr[i], x = xr[i];
        s = fmaf(w.x, x.x, fmaf(w.y, x.y, fmaf(w.z, x.z, fmaf(w.w, x.w, s))));
    }
    g_pd[b * A_ + tid] = s + att_b[tid];
}

// ---------------------------------------------------------------------------
// K2: fp16 m16n8k16 mma.sync score GEMM (fp32 accum), cp.async pipeline,
//     FIR + bias folded as extra K chunks.  8 warps; warp tile 64x32.
// ---------------------------------------------------------------------------
__global__ void __launch_bounds__(256, 2)
k_score(const float* __restrict__ enc, const float* __restrict__ enc_w,
        const float* __restrict__ prev_att, const float* __restrict__ out_w,
        const int* __restrict__ lengths)
{
    extern __shared__ float dsm[];

    const int b     = blockIdx.y;
    const int trow0 = blockIdx.x * TILE_M;
    const int tid   = threadIdx.x;
    const int lane  = tid & 31;
    const int wid   = tid >> 5;
    const int warp_m = wid & 1;
    const int warp_n = wid >> 1;
    const int g     = lane >> 2;
    const int tg    = lane & 3;
    const int r     = tid >> 2;     // loader row 0..63 (covers r and r+64)
    const int q     = tid & 3;      // loader quad

    const int len = lengths[b];
    if (trow0 >= len) {             // fully masked tile
        for (int i = tid; i < TILE_M; i += 256) {
            int t = trow0 + i;
            if (t < T_) g_score[b * T_ + t] = -INFINITY;
        }
        return;
    }

    float* spatt = dsm + SPATT_O;
    float* s_ow  = dsm + SOW_O;
    float* sred  = dsm + SRED_O;

    for (int i = tid; i < TILE_M + 2 * FS_; i += 256) {
        int t = trow0 + i - FS_;
        spatt[i] = (t >= 0 && t < T_) ? prev_att[b * T_ + t] : 0.f;
    }
    if (tid < A_) s_ow[tid] = out_w[tid];

    const uint32_t sbase = smem_u32(dsm);
    uint64_t gA, gW;
    {
        const float* Abase = enc + ((size_t)b * T_ + trow0) * DE_;
        asm("cvta.to.global.u64 %0, %1;" : "=l"(gA) : "l"(Abase));
        asm("cvta.to.global.u64 %0, %1;" : "=l"(gW) : "l"(enc_w));
    }
    const int szA0 = (trow0 + r      < T_) ? 16 : 0;
    const int szA1 = (trow0 + r + 64 < T_) ? 16 : 0;
    const uint32_t soff     = (uint32_t)(r * LDS_ + 4 * q) * 4u;
    const uint32_t rowskip  = 64u * LDS_ * 4u;
    const uint64_t goff     = ((size_t)r * DE_ + 4 * q) * 4;
    const uint64_t growskip = (size_t)64 * DE_ * 4;

    auto issue = [&](int c) {
        const int bi = c & 3;
        const uint32_t da = sbase + (uint32_t)ABUF(bi) * 4u + soff;
        const uint32_t db = sbase + (uint32_t)BBUF(bi) * 4u + soff;
        const uint64_t off = goff + (uint64_t)c * (BKF * 4);
        cp16(da,           gA + off,            szA0);
        cp16(da + rowskip, gA + off + growskip, szA1);
        cp16(db,           gW + off,            16);
        cp16(db + rowskip, gW + off + growskip, 16);
        asm volatile("cp.async.commit_group;" ::: "memory");
    };

    float acc[4][4][4];
#pragma unroll
    for (int mi = 0; mi < 4; ++mi)
#pragma unroll
        for (int ni = 0; ni < 4; ++ni)
#pragma unroll
            for (int j = 0; j < 4; ++j) acc[mi][ni][j] = 0.f;

    // one m16n8k16 slab per chunk: fp16 fragments packed from fp32 smem
    auto compute = [&](int bi) {
        const float* Ad = dsm + ABUF(bi);
        const float* Bd = dsm + BBUF(bi);
        const int k0 = 2 * tg;
        uint32_t bf[4][2];
#pragma unroll
        for (int ni = 0; ni < 4; ++ni) {
            int nb = warp_n * 32 + ni * 8 + g;
            bf[ni][0] = packh2(Bd + nb * LDS_ + k0);
            bf[ni][1] = packh2(Bd + nb * LDS_ + k0 + 8);
        }
#pragma unroll
        for (int mi = 0; mi < 4; ++mi) {
            int rb = warp_m * 64 + mi * 16 + g;
            uint32_t af[4];
            af[0] = packh2(Ad + rb * LDS_ + k0);
            af[1] = packh2(Ad + (rb + 8) * LDS_ + k0);
            af[2] = packh2(Ad + rb * LDS_ + k0 + 8);
            af[3] = packh2(Ad + (rb + 8) * LDS_ + k0 + 8);
#pragma unroll
            for (int ni = 0; ni < 4; ++ni)
                mma_f16(acc[mi][ni], af, bf[ni]);
        }
    };

    auto extsts = [&](int e, int bi) {
        float* Ad = dsm + ABUF(bi);
        float* Bd = dsm + BBUF(bi);
        const float4 z4 = make_float4(0.f, 0.f, 0.f, 0.f);
#pragma unroll
        for (int h = 0; h < 2; ++h) {
            const int rr = r + 64 * h;
            float4 av, bv;
            if (e < 2) {
                const int kk = 16 * e + 4 * q;
                av = make_float4(spatt[rr + kk], spatt[rr + kk + 1],
                                 spatt[rr + kk + 2], spatt[rr + kk + 3]);
                bv = make_float4(g_eff[(kk + 0) * A_ + rr], g_eff[(kk + 1) * A_ + rr],
                                 g_eff[(kk + 2) * A_ + rr], g_eff[(kk + 3) * A_ + rr]);
            } else {
                av = z4; bv = z4;
                if (q == 0) {
                    av.x = spatt[rr + 32]; av.y = 1.0f;
                    bv.x = g_eff[32 * A_ + rr]; bv.y = g_pd[b * A_ + rr];
                }
            }
            *(float4*)(Ad + rr * LDS_ + 4 * q) = av;
            *(float4*)(Bd + rr * LDS_ + 4 * q) = bv;
        }
    };

    // ---- pipelined mainloop: depth-3 prefetch over 4 buffers ----
    // (issue placed AFTER the barrier so buf (c+3)&3 == (c-1)&3 is reuse-safe)
    issue(0); issue(1); issue(2);
    for (int c = 0; c < NCHG; ++c) {
        if (c + 2 < NCHG) {
            asm volatile("cp.async.wait_group 2;" ::: "memory");
        } else if (c + 1 < NCHG) {
            asm volatile("cp.async.wait_group 1;" ::: "memory");
        } else {
            asm volatile("cp.async.wait_group 0;" ::: "memory");
        }
        __syncthreads();
        if (c + 3 < NCHG) issue(c + 3);
        compute(c & 3);
    }

    // ---- ext chunks in bufs 0,1,2 (chunk 31 computed on buf 3) ----
    extsts(0, 0); extsts(1, 1); extsts(2, 2);
    __syncthreads();
    compute(0); compute(1); compute(2);

    // ---- epilogue: tanh + out_w dot, reduce over a-dimension ----
    float ow0[4], ow1[4];
#pragma unroll
    for (int ni = 0; ni < 4; ++ni) {
        int c0 = warp_n * 32 + ni * 8 + 2 * tg;
        ow0[ni] = s_ow[c0]; ow1[ni] = s_ow[c0 + 1];
    }
#pragma unroll
    for (int mi = 0; mi < 4; ++mi) {
        float p0 = 0.f, p1 = 0.f;
#pragma unroll
        for (int ni = 0; ni < 4; ++ni) {
            p0 = fmaf(ow0[ni], tanhf(acc[mi][ni][0]), p0);
            p0 = fmaf(ow1[ni], tanhf(acc[mi][ni][1]), p0);
            p1 = fmaf(ow0[ni], tanhf(acc[mi][ni][2]), p1);
            p1 = fmaf(ow1[ni], tanhf(acc[mi][ni][3]), p1);
        }
        p0 += __shfl_down_sync(0xffffffffu, p0, 2, 4);
        p0 += __shfl_down_sync(0xffffffffu, p0, 1, 4);
        p1 += __shfl_down_sync(0xffffffffu, p1, 2, 4);
        p1 += __shfl_down_sync(0xffffffffu, p1, 1, 4);
        if (tg == 0) {
            int rb = warp_m * 64 + mi * 16 + g;
            sred[warp_n * TILE_M + rb] = p0;
            sred[warp_n * TILE_M + rb + 8] = p1;
        }
    }
    __syncthreads();

    if (tid < TILE_M) {
        int t = trow0 + tid;
        if (t < T_) {
            float s = sred[tid] + sred[TILE_M + tid] +
                      sred[2 * TILE_M + tid] + sred[3 * TILE_M + tid];
            g_score[b * T_ + t] = (t < len) ? s : -INFINITY;
        }
    }
}

// ---------------------------------------------------------------------------
// K3: per-batch softmax stats (max, 1/sum).  grid B_, 1024 threads.
// ---------------------------------------------------------------------------
__global__ void k_stats() {
    int b = blockIdx.x, tid = threadIdx.x;
    __shared__ float red[32];
    __shared__ float s_m;
    const float* sc = g_score + b * T_;

    float m = -INFINITY;
    for (int t = tid; t < T_; t += 1024) m = fmaxf(m, sc[t]);
#pragma unroll
    for (int o = 16; o; o >>= 1) m = fmaxf(m, __shfl_xor_sync(0xffffffffu, m, o));
    if ((tid & 31) == 0) red[tid >> 5] = m;
    __syncthreads();
    if (tid < 32) {
        float v = red[tid];
#pragma unroll
        for (int o = 16; o; o >>= 1) v = fmaxf(v, __shfl_xor_sync(0xffffffffu, v, o));
        if (tid == 0) s_m = v;
    }
    __syncthreads();
    m = s_m;

    float s = 0.f;
    for (int t = tid; t < T_; t += 1024) s += expf(sc[t] - m);
#pragma unroll
    for (int o = 16; o; o >>= 1) s += __shfl_xor_sync(0xffffffffu, s, o);
    if ((tid & 31) == 0) red[tid >> 5] = s;
    __syncthreads();
    if (tid < 32) {
        float v = red[tid];
#pragma unroll
        for (int o = 16; o; o >>= 1) v += __shfl_xor_sync(0xffffffffu, v, o);
        if (tid == 0) { g_stats[2 * b] = m; g_stats[2 * b + 1] = 1.f / v; }
    }
}

// ---------------------------------------------------------------------------
// K4: fused att-weight write + context atomic accumulate.
//     grid (B_, SEG_), 512 threads.
// ---------------------------------------------------------------------------
__global__ void k_ctx(const float* __restrict__ enc, float* __restrict__ att_out,
                      float* __restrict__ ctx_out, const int* __restrict__ lengths) {
    int b = blockIdx.x, seg = blockIdx.y, tid = threadIdx.x;
    __shared__ float w[TSEG];
    const float m = g_stats[2 * b], inv = g_stats[2 * b + 1];
    const int t0 = seg * TSEG;
    if (tid < TSEG) {
        float sc = g_score[b * T_ + t0 + tid];
        float wv = expf(sc - m) * inv;       // exp(-inf)=0 handles the mask
        w[tid] = wv;
        att_out[b * T_ + t0 + tid] = wv;
    }
    __syncthreads();
    const int len = lengths[b];
    const int n = min(TSEG, max(0, len - t0));
    float s = 0.f;
    const float* e = enc + ((size_t)b * T_ + t0) * DE_ + tid;
#pragma unroll 4
    for (int tt = 0; tt < n; ++tt) s = fmaf(w[tt], e[(size_t)tt * DE_], s);
    if (n > 0) atomicAdd(&ctx_out[b * DE_ + tid], s);
}

// ---------------------------------------------------------------------------
// Entry point
// ---------------------------------------------------------------------------
extern "C" void kernel_launch(void* const* d_in, const int* in_sizes, int n_in,
                              void* d_out, int out_size) {
    const float* input_enc   = (const float*)d_in[0];
    const int*   enc_lengths = (const int*)  d_in[1];
    const float* input_dec   = (const float*)d_in[2];
    const float* prev_att    = (const float*)d_in[3];
    const float* conv_w      = (const float*)d_in[4];
    const float* enc_w       = (const float*)d_in[5];
    const float* dec_w       = (const float*)d_in[6];
    const float* att_w       = (const float*)d_in[7];
    const float* att_b       = (const float*)d_in[8];
    const float* out_w       = (const float*)d_in[9];

    float* ctx_out = (float*)d_out;            // [B, DE]
    float* att_out = ctx_out + B_ * DE_;       // [B, T]

    static int attr_set = 0;
    if (!attr_set) {
        cudaFuncSetAttribute(k_score, cudaFuncAttributeMaxDynamicSharedMemorySize,
                             SMEM_FLOATS * 4);
        attr_set = 1;
    }

    k_eff<<<1, 128>>>(att_w, conv_w);                  // idx 0
    k_zero<<<B_, 512>>>(ctx_out);                      // idx 1
    k_pd<<<B_, 128>>>(dec_w, input_dec, att_b);        // idx 2
    k_score<<<dim3((T_ + TILE_M - 1) / TILE_M, B_), 256, SMEM_FLOATS * 4>>>(
        input_enc, enc_w, prev_att, out_w, enc_lengths);   // idx 3 (ncu target)
    k_stats<<<B_, 1024>>>();                           // idx 4
    k_ctx<<<dim3(B_, SEG_), 512>>>(input_enc, att_out, ctx_out, enc_lengths);  // idx 5
}

// round 12
// speedup vs baseline: 3.1481x; 1.1765x over previous
#include <cuda_runtime.h>
#include <math.h>
#include <stdint.h>

// Problem constants
#define B_   32
#define T_   2000
#define DE_  512
#define DD_  1024
#define A_   128
#define FN_  32
#define FS_  16
#define KW_  33

#define TILE_M 128
#define BKF    16            // K floats per chunk (= one m16n8k16 slab)
#define NCHG   32            // gmem K-chunks (512/16)
#define LDS_   24            // padded smem row stride (floats): conflict-free for LDS.64
#define SEG_   20
#define TSEG   (T_/SEG_)     // 100

// dynamic smem layout (float offsets): 4 A bufs, 4 B bufs, spatt, ow, red
#define ABUF(i)  ((i) * 3072)             // 128*24
#define BBUF(i)  (12288 + (i) * 3072)
#define SPATT_O  24576
#define SOW_O    24736
#define SRED_O   24864
#define SMEM_FLOATS 25376                 // 101504 bytes

// Scratch (no cudaMalloc allowed)
__device__ float g_eff[KW_ * A_];        // eff[k][a]
__device__ float g_pd[B_ * A_];          // dec projection + att_b
__device__ float g_score[B_ * T_];
__device__ float g_stats[B_ * 2];        // max, 1/sum

__device__ __forceinline__ uint32_t smem_u32(const void* p) {
    uint32_t a;
    asm("{ .reg .u64 t; cvta.to.shared.u64 t, %1; cvt.u32.u64 %0, t; }" : "=r"(a) : "l"(p));
    return a;
}
__device__ __forceinline__ void cp16(uint32_t dst, uint64_t src, int srcsz) {
    asm volatile("cp.async.cg.shared.global [%0], [%1], 16, %2;"
                 :: "r"(dst), "l"(src), "r"(srcsz) : "memory");
}
// load two consecutive k floats, round to fp16 pair {lo=k, hi=k+1}
__device__ __forceinline__ uint32_t packh2(const float* p) {
    float2 v = *(const float2*)p;
    uint32_t r;
    asm("cvt.rn.f16x2.f32 %0, %1, %2;" : "=r"(r) : "f"(v.y), "f"(v.x));
    return r;
}
__device__ __forceinline__ void mma_f16(float* d, const uint32_t* a, const uint32_t* bb) {
    asm volatile(
        "mma.sync.aligned.m16n8k16.row.col.f32.f16.f16.f32 "
        "{%0,%1,%2,%3}, {%4,%5,%6,%7}, {%8,%9}, {%0,%1,%2,%3};"
        : "+f"(d[0]), "+f"(d[1]), "+f"(d[2]), "+f"(d[3])
        : "r"(a[0]), "r"(a[1]), "r"(a[2]), "r"(a[3]), "r"(bb[0]), "r"(bb[1]));
}

// ---------------------------------------------------------------------------
// K0 (idx 0): prep — fold conv through att_w (block 0), decoder projection
//             + att_b (block b), zero ctx accumulators.  grid B_, 128 threads.
// ---------------------------------------------------------------------------
__global__ void k_prep(const float* __restrict__ att_w, const float* __restrict__ conv_w,
                       const float* __restrict__ dec_w, const float* __restrict__ input_dec,
                       const float* __restrict__ att_b, float* __restrict__ ctx_out) {
    __shared__ float sdec[DD_];
    int b = blockIdx.x, tid = threadIdx.x;

    // zero ctx accumulators (graph-replay safe: redone every launch)
#pragma unroll
    for (int i = 0; i < 4; ++i) ctx_out[b * DE_ + i * 128 + tid] = 0.f;

    // block 0: eff[k][a] = sum_f att_w[a,f]*conv_w[f,k]
    if (b == 0) {
        int a = tid;
        float aw[FN_];
#pragma unroll
        for (int f = 0; f < FN_; ++f) aw[f] = att_w[a * FN_ + f];
        for (int k = 0; k < KW_; ++k) {
            float s = 0.f;
#pragma unroll
            for (int f = 0; f < FN_; ++f) s = fmaf(aw[f], conv_w[f * KW_ + k], s);
            g_eff[k * A_ + a] = s;
        }
    }

    // decoder projection
    for (int i = tid; i < DD_; i += blockDim.x) sdec[i] = input_dec[b * DD_ + i];
    __syncthreads();
    const float4* wr = (const float4*)(dec_w + (size_t)tid * DD_);
    const float4* xr = (const float4*)sdec;
    float s = 0.f;
#pragma unroll 4
    for (int i = 0; i < DD_ / 4; ++i) {
        float4 w = wr[i], x = xr[i];
        s = fmaf(w.x, x.x, fmaf(w.y, x.y, fmaf(w.z, x.z, fmaf(w.w, x.w, s))));
    }
    g_pd[b * A_ + tid] = s + att_b[tid];
}

// ---------------------------------------------------------------------------
// K1 (idx 1): fp16 m16n8k16 mma.sync score GEMM (fp32 accum), cp.async
//     pipeline, FIR + bias folded as extra K chunks.  8 warps; warp tile 64x32.
// ---------------------------------------------------------------------------
__global__ void __launch_bounds__(256, 2)
k_score(const float* __restrict__ enc, const float* __restrict__ enc_w,
        const float* __restrict__ prev_att, const float* __restrict__ out_w,
        const int* __restrict__ lengths)
{
    extern __shared__ float dsm[];

    const int b     = blockIdx.y;
    const int trow0 = blockIdx.x * TILE_M;
    const int tid   = threadIdx.x;
    const int lane  = tid & 31;
    const int wid   = tid >> 5;
    const int warp_m = wid & 1;
    const int warp_n = wid >> 1;
    const int g     = lane >> 2;
    const int tg    = lane & 3;
    const int r     = tid >> 2;     // loader row 0..63 (covers r and r+64)
    const int q     = tid & 3;      // loader quad

    const int len = lengths[b];
    if (trow0 >= len) {             // fully masked tile
        for (int i = tid; i < TILE_M; i += 256) {
            int t = trow0 + i;
            if (t < T_) g_score[b * T_ + t] = -INFINITY;
        }
        return;
    }

    float* spatt = dsm + SPATT_O;
    float* s_ow  = dsm + SOW_O;
    float* sred  = dsm + SRED_O;

    for (int i = tid; i < TILE_M + 2 * FS_; i += 256) {
        int t = trow0 + i - FS_;
        spatt[i] = (t >= 0 && t < T_) ? prev_att[b * T_ + t] : 0.f;
    }
    if (tid < A_) s_ow[tid] = out_w[tid];

    const uint32_t sbase = smem_u32(dsm);
    uint64_t gA, gW;
    {
        const float* Abase = enc + ((size_t)b * T_ + trow0) * DE_;
        asm("cvta.to.global.u64 %0, %1;" : "=l"(gA) : "l"(Abase));
        asm("cvta.to.global.u64 %0, %1;" : "=l"(gW) : "l"(enc_w));
    }
    const int szA0 = (trow0 + r      < T_) ? 16 : 0;
    const int szA1 = (trow0 + r + 64 < T_) ? 16 : 0;
    const uint32_t soff     = (uint32_t)(r * LDS_ + 4 * q) * 4u;
    const uint32_t rowskip  = 64u * LDS_ * 4u;
    const uint64_t goff     = ((size_t)r * DE_ + 4 * q) * 4;
    const uint64_t growskip = (size_t)64 * DE_ * 4;

    auto issue = [&](int c) {
        const int bi = c & 3;
        const uint32_t da = sbase + (uint32_t)ABUF(bi) * 4u + soff;
        const uint32_t db = sbase + (uint32_t)BBUF(bi) * 4u + soff;
        const uint64_t off = goff + (uint64_t)c * (BKF * 4);
        cp16(da,           gA + off,            szA0);
        cp16(da + rowskip, gA + off + growskip, szA1);
        cp16(db,           gW + off,            16);
        cp16(db + rowskip, gW + off + growskip, 16);
        asm volatile("cp.async.commit_group;" ::: "memory");
    };

    float acc[4][4][4];
#pragma unroll
    for (int mi = 0; mi < 4; ++mi)
#pragma unroll
        for (int ni = 0; ni < 4; ++ni)
#pragma unroll
            for (int j = 0; j < 4; ++j) acc[mi][ni][j] = 0.f;

    auto compute = [&](int bi) {
        const float* Ad = dsm + ABUF(bi);
        const float* Bd = dsm + BBUF(bi);
        const int k0 = 2 * tg;
        uint32_t bf[4][2];
#pragma unroll
        for (int ni = 0; ni < 4; ++ni) {
            int nb = warp_n * 32 + ni * 8 + g;
            bf[ni][0] = packh2(Bd + nb * LDS_ + k0);
            bf[ni][1] = packh2(Bd + nb * LDS_ + k0 + 8);
        }
#pragma unroll
        for (int mi = 0; mi < 4; ++mi) {
            int rb = warp_m * 64 + mi * 16 + g;
            uint32_t af[4];
            af[0] = packh2(Ad + rb * LDS_ + k0);
            af[1] = packh2(Ad + (rb + 8) * LDS_ + k0);
            af[2] = packh2(Ad + rb * LDS_ + k0 + 8);
            af[3] = packh2(Ad + (rb + 8) * LDS_ + k0 + 8);
#pragma unroll
            for (int ni = 0; ni < 4; ++ni)
                mma_f16(acc[mi][ni], af, bf[ni]);
        }
    };

    auto extsts = [&](int e, int bi) {
        float* Ad = dsm + ABUF(bi);
        float* Bd = dsm + BBUF(bi);
        const float4 z4 = make_float4(0.f, 0.f, 0.f, 0.f);
#pragma unroll
        for (int h = 0; h < 2; ++h) {
            const int rr = r + 64 * h;
            float4 av, bv;
            if (e < 2) {
                const int kk = 16 * e + 4 * q;
                av = make_float4(spatt[rr + kk], spatt[rr + kk + 1],
                                 spatt[rr + kk + 2], spatt[rr + kk + 3]);
                bv = make_float4(g_eff[(kk + 0) * A_ + rr], g_eff[(kk + 1) * A_ + rr],
                                 g_eff[(kk + 2) * A_ + rr], g_eff[(kk + 3) * A_ + rr]);
            } else {
                av = z4; bv = z4;
                if (q == 0) {
                    av.x = spatt[rr + 32]; av.y = 1.0f;
                    bv.x = g_eff[32 * A_ + rr]; bv.y = g_pd[b * A_ + rr];
                }
            }
            *(float4*)(Ad + rr * LDS_ + 4 * q) = av;
            *(float4*)(Bd + rr * LDS_ + 4 * q) = bv;
        }
    };

    // ---- pipelined mainloop: depth-3 prefetch over 4 buffers ----
    issue(0); issue(1); issue(2);
    for (int c = 0; c < NCHG; ++c) {
        if (c + 2 < NCHG) {
            asm volatile("cp.async.wait_group 2;" ::: "memory");
        } else if (c + 1 < NCHG) {
            asm volatile("cp.async.wait_group 1;" ::: "memory");
        } else {
            asm volatile("cp.async.wait_group 0;" ::: "memory");
        }
        __syncthreads();
        if (c + 3 < NCHG) issue(c + 3);
        compute(c & 3);
    }

    // ---- ext chunks in bufs 0,1,2 (chunk 31 computed on buf 3) ----
    extsts(0, 0); extsts(1, 1); extsts(2, 2);
    __syncthreads();
    compute(0); compute(1); compute(2);

    // ---- epilogue: tanh + out_w dot, reduce over a-dimension ----
    float ow0[4], ow1[4];
#pragma unroll
    for (int ni = 0; ni < 4; ++ni) {
        int c0 = warp_n * 32 + ni * 8 + 2 * tg;
        ow0[ni] = s_ow[c0]; ow1[ni] = s_ow[c0 + 1];
    }
#pragma unroll
    for (int mi = 0; mi < 4; ++mi) {
        float p0 = 0.f, p1 = 0.f;
#pragma unroll
        for (int ni = 0; ni < 4; ++ni) {
            p0 = fmaf(ow0[ni], tanhf(acc[mi][ni][0]), p0);
            p0 = fmaf(ow1[ni], tanhf(acc[mi][ni][1]), p0);
            p1 = fmaf(ow0[ni], tanhf(acc[mi][ni][2]), p1);
            p1 = fmaf(ow1[ni], tanhf(acc[mi][ni][3]), p1);
        }
        p0 += __shfl_down_sync(0xffffffffu, p0, 2, 4);
        p0 += __shfl_down_sync(0xffffffffu, p0, 1, 4);
        p1 += __shfl_down_sync(0xffffffffu, p1, 2, 4);
        p1 += __shfl_down_sync(0xffffffffu, p1, 1, 4);
        if (tg == 0) {
            int rb = warp_m * 64 + mi * 16 + g;
            sred[warp_n * TILE_M + rb] = p0;
            sred[warp_n * TILE_M + rb + 8] = p1;
        }
    }
    __syncthreads();

    if (tid < TILE_M) {
        int t = trow0 + tid;
        if (t < T_) {
            float s = sred[tid] + sred[TILE_M + tid] +
                      sred[2 * TILE_M + tid] + sred[3 * TILE_M + tid];
            g_score[b * T_ + t] = (t < len) ? s : -INFINITY;
        }
    }
}

// ---------------------------------------------------------------------------
// K2 (idx 2): per-batch softmax stats (max, 1/sum).  grid B_, 1024 threads.
// ---------------------------------------------------------------------------
__global__ void k_stats() {
    int b = blockIdx.x, tid = threadIdx.x;
    __shared__ float red[32];
    __shared__ float s_m;
    const float* sc = g_score + b * T_;

    float m = -INFINITY;
    for (int t = tid; t < T_; t += 1024) m = fmaxf(m, sc[t]);
#pragma unroll
    for (int o = 16; o; o >>= 1) m = fmaxf(m, __shfl_xor_sync(0xffffffffu, m, o));
    if ((tid & 31) == 0) red[tid >> 5] = m;
    __syncthreads();
    if (tid < 32) {
        float v = red[tid];
#pragma unroll
        for (int o = 16; o; o >>= 1) v = fmaxf(v, __shfl_xor_sync(0xffffffffu, v, o));
        if (tid == 0) s_m = v;
    }
    __syncthreads();
    m = s_m;

    float s = 0.f;
    for (int t = tid; t < T_; t += 1024) s += expf(sc[t] - m);
#pragma unroll
    for (int o = 16; o; o >>= 1) s += __shfl_xor_sync(0xffffffffu, s, o);
    if ((tid & 31) == 0) red[tid >> 5] = s;
    __syncthreads();
    if (tid < 32) {
        float v = red[tid];
#pragma unroll
        for (int o = 16; o; o >>= 1) v += __shfl_xor_sync(0xffffffffu, v, o);
        if (tid == 0) { g_stats[2 * b] = m; g_stats[2 * b + 1] = 1.f / v; }
    }
}

// ---------------------------------------------------------------------------
// K3 (idx 3 — ncu target): att-weight write + context accumulate.
//     grid (B_, SEG_), 512 threads = 4 row-groups x 128 d-lanes (float4).
// ---------------------------------------------------------------------------
__global__ void __launch_bounds__(512)
k_ctx(const float* __restrict__ enc, float* __restrict__ att_out,
      float* __restrict__ ctx_out, const int* __restrict__ lengths) {
    int b = blockIdx.x, seg = blockIdx.y, tid = threadIdx.x;
    __shared__ float w[TSEG];
    __shared__ float4 red4[3][128];
    const float m = g_stats[2 * b], inv = g_stats[2 * b + 1];
    const int t0 = seg * TSEG;
    if (tid < TSEG) {
        float sc = g_score[b * T_ + t0 + tid];
        float wv = expf(sc - m) * inv;       // exp(-inf)=0 handles the mask
        w[tid] = wv;
        att_out[b * T_ + t0 + tid] = wv;
    }
    __syncthreads();

    const int len = lengths[b];
    const int n = min(TSEG, max(0, len - t0));
    if (n <= 0) return;

    const int grp = tid >> 7;        // 0..3 (row group)
    const int dl  = tid & 127;       // d-lane (float4 index)
    const float4* e = (const float4*)(enc + ((size_t)b * T_ + t0) * DE_) + dl;

    float4 acc = make_float4(0.f, 0.f, 0.f, 0.f);
#pragma unroll 4
    for (int tt = grp; tt < n; tt += 4) {
        float wv = w[tt];
        float4 v = e[(size_t)tt * (DE_ / 4)];
        acc.x = fmaf(wv, v.x, acc.x);
        acc.y = fmaf(wv, v.y, acc.y);
        acc.z = fmaf(wv, v.z, acc.z);
        acc.w = fmaf(wv, v.w, acc.w);
    }

    if (grp > 0) red4[grp - 1][dl] = acc;
    __syncthreads();
    if (grp == 0) {
#pragma unroll
        for (int j = 0; j < 3; ++j) {
            float4 v = red4[j][dl];
            acc.x += v.x; acc.y += v.y; acc.z += v.z; acc.w += v.w;
        }
        float* dst = ctx_out + b * DE_ + dl * 4;
        atomicAdd(dst + 0, acc.x);
        atomicAdd(dst + 1, acc.y);
        atomicAdd(dst + 2, acc.z);
        atomicAdd(dst + 3, acc.w);
    }
}

// ---------------------------------------------------------------------------
// Entry point
// ---------------------------------------------------------------------------
extern "C" void kernel_launch(void* const* d_in, const int* in_sizes, int n_in,
                              void* d_out, int out_size) {
    const float* input_enc   = (const float*)d_in[0];
    const int*   enc_lengths = (const int*)  d_in[1];
    const float* input_dec   = (const float*)d_in[2];
    const float* prev_att    = (const float*)d_in[3];
    const float* conv_w      = (const float*)d_in[4];
    const float* enc_w       = (const float*)d_in[5];
    const float* dec_w       = (const float*)d_in[6];
    const float* att_w       = (const float*)d_in[7];
    const float* att_b       = (const float*)d_in[8];
    const float* out_w       = (const float*)d_in[9];

    float* ctx_out = (float*)d_out;            // [B, DE]
    float* att_out = ctx_out + B_ * DE_;       // [B, T]

    static int attr_set = 0;
    if (!attr_set) {
        cudaFuncSetAttribute(k_score, cudaFuncAttributeMaxDynamicSharedMemorySize,
                             SMEM_FLOATS * 4);
        attr_set = 1;
    }

    k_prep<<<B_, 128>>>(att_w, conv_w, dec_w, input_dec, att_b, ctx_out);   // idx 0
    k_score<<<dim3((T_ + TILE_M - 1) / TILE_M, B_), 256, SMEM_FLOATS * 4>>>(
        input_enc, enc_w, prev_att, out_w, enc_lengths);                    // idx 1
    k_stats<<<B_, 1024>>>();                                                // idx 2
    k_ctx<<<dim3(B_, SEG_), 512>>>(input_enc, att_out, ctx_out, enc_lengths); // idx 3
}